// round 4
// baseline (speedup 1.0000x reference)
#include <cuda_runtime.h>
#include <math.h>

#define BB 4
#define CC 64
#define OCH 64
#define HH 256
#define WW 256
#define PP 64
#define NBLK (BB * HH * (WW / PP))   // 4096 blocks

__device__ float g_psum  [OCH * NBLK];
__device__ float g_psumsq[OCH * NBLK];
__device__ float g_scale [OCH];
__device__ float g_shift [OCH];

__device__ __forceinline__ float fetch_px(const float* __restrict__ img, int y, int x) {
    if ((unsigned)y < (unsigned)HH && (unsigned)x < (unsigned)WW)
        return __ldg(img + y * WW + x);
    return 0.0f;
}

__global__ __launch_bounds__(256, 3)
void fused_deform_kernel(const float* __restrict__ x,
                         const float* __restrict__ dw,
                         const float* __restrict__ pw,
                         const float* __restrict__ w2,
                         const float* __restrict__ bias,
                         float* __restrict__ out)
{
    __shared__ float s_t   [CC * PP];   // dwconv output  t[c][p]   (16 KB)
    __shared__ float s_samp[CC * PP];   // sampled*mod    s[c][p]   (16 KB)

    const int tid = threadIdx.x;
    const int w0  = blockIdx.x * PP;
    const int h   = blockIdx.y;
    const int b   = blockIdx.z;
    const int bid = (blockIdx.z * gridDim.y + blockIdx.y) * gridDim.x + blockIdx.x;

    // ---- stage 1: depthwise 3x3 conv, vectorized: (channel, 4px) units ----
    {
        #pragma unroll
        for (int u = 0; u < 4; u++) {
            const int unit = tid + 256 * u;      // 0..1023
            const int c  = unit >> 4;            // 0..63
            const int g  = unit & 15;            // 0..15 (4-px group)
            const int xs = w0 + g * 4;           // start pixel (16B aligned)
            const float* xc = x + ((size_t)(b * CC + c)) * (HH * WW);
            float w9[9];
            #pragma unroll
            for (int i = 0; i < 9; i++) w9[i] = __ldg(dw + c * 9 + i);

            float a0 = 0.f, a1 = 0.f, a2 = 0.f, a3 = 0.f;
            #pragma unroll
            for (int dy = -1; dy <= 1; dy++) {
                const int y = h + dy;
                if ((unsigned)y < (unsigned)HH) {
                    const float* row = xc + y * WW;
                    const float4 m = *reinterpret_cast<const float4*>(row + xs);
                    const float lm = (xs - 1 >= 0) ? __ldg(row + xs - 1) : 0.0f;
                    const float rm = (xs + 4 < WW) ? __ldg(row + xs + 4) : 0.0f;
                    const float wl = w9[(dy + 1) * 3 + 0];
                    const float wm = w9[(dy + 1) * 3 + 1];
                    const float wr = w9[(dy + 1) * 3 + 2];
                    a0 += wl * lm  + wm * m.x + wr * m.y;
                    a1 += wl * m.x + wm * m.y + wr * m.z;
                    a2 += wl * m.y + wm * m.z + wr * m.w;
                    a3 += wl * m.z + wm * m.w + wr * rm;
                }
            }
            float4 r; r.x = a0; r.y = a1; r.z = a2; r.w = a3;
            *reinterpret_cast<float4*>(&s_t[c * 64 + g * 4]) = r;
        }
    }
    __syncthreads();

    // ---- stage 2: per-warp 24-row (8-channel) matvec, 2 px per lane -------
    // warp wid owns channels 8*wid .. 8*wid+7:
    //   offset-y rows 16*wid+2i, offset-x rows 16*wid+2i+1, mod rows 128+8*wid+i
    const int wid  = tid >> 5;           // 0..7
    const int lane = tid & 31;
    const int p0   = lane * 2;           // 2 pixels per lane

    float accY[8][2], accX[8][2], accM[8][2];
    #pragma unroll
    for (int i = 0; i < 8; i++) {
        accY[i][0] = accY[i][1] = 0.0f;
        accX[i][0] = accX[i][1] = 0.0f;
        accM[i][0] = accM[i][1] = 0.0f;
    }

    const float4* pw4 = (const float4*)pw;
    #pragma unroll 2
    for (int c4 = 0; c4 < 64; c4 += 4) {
        const float2 tv0 = *reinterpret_cast<const float2*>(&s_t[(c4 + 0) * 64 + p0]);
        const float2 tv1 = *reinterpret_cast<const float2*>(&s_t[(c4 + 1) * 64 + p0]);
        const float2 tv2 = *reinterpret_cast<const float2*>(&s_t[(c4 + 2) * 64 + p0]);
        const float2 tv3 = *reinterpret_cast<const float2*>(&s_t[(c4 + 3) * 64 + p0]);
        const int cidx = c4 >> 2;
        #pragma unroll
        for (int i = 0; i < 8; i++) {
            const float4 wY = __ldg(&pw4[(16 * wid + 2 * i)     * 16 + cidx]);
            accY[i][0] += wY.x * tv0.x + wY.y * tv1.x + wY.z * tv2.x + wY.w * tv3.x;
            accY[i][1] += wY.x * tv0.y + wY.y * tv1.y + wY.z * tv2.y + wY.w * tv3.y;
            const float4 wX = __ldg(&pw4[(16 * wid + 2 * i + 1) * 16 + cidx]);
            accX[i][0] += wX.x * tv0.x + wX.y * tv1.x + wX.z * tv2.x + wX.w * tv3.x;
            accX[i][1] += wX.x * tv0.y + wX.y * tv1.y + wX.z * tv2.y + wX.w * tv3.y;
            const float4 wM = __ldg(&pw4[(128 + 8 * wid + i)    * 16 + cidx]);
            accM[i][0] += wM.x * tv0.x + wM.y * tv1.x + wM.z * tv2.x + wM.w * tv3.x;
            accM[i][1] += wM.x * tv0.y + wM.y * tv1.y + wM.z * tv2.y + wM.w * tv3.y;
        }
    }

    // ---- stage 3: bilinear sampling * modulator -> s_samp -----------------
    #pragma unroll
    for (int i = 0; i < 8; i++) {
        const int c = 8 * wid + i;
        const float* xc = x + ((size_t)(b * CC + c)) * (HH * WW);
        float2 sv;
        float* svp = &sv.x;
        #pragma unroll
        for (int r = 0; r < 2; r++) {
            const float offy = fminf(fmaxf(accY[i][r], -64.0f), 64.0f);
            const float offx = fminf(fmaxf(accX[i][r], -64.0f), 64.0f);
            const float md   = 2.0f / (1.0f + __expf(-accM[i][r]));
            const float sy = (float)h + offy;
            const float sx = (float)(w0 + p0 + r) + offx;
            const float y0f = floorf(sy);
            const float x0f = floorf(sx);
            const float wy = sy - y0f;
            const float wx = sx - x0f;
            const int y0  = (int)y0f;
            const int x0i = (int)x0f;
            const float v00 = fetch_px(xc, y0,     x0i);
            const float v01 = fetch_px(xc, y0,     x0i + 1);
            const float v10 = fetch_px(xc, y0 + 1, x0i);
            const float v11 = fetch_px(xc, y0 + 1, x0i + 1);
            const float val = (1.0f - wy) * ((1.0f - wx) * v00 + wx * v01)
                            +         wy  * ((1.0f - wx) * v10 + wx * v11);
            svp[r] = val * md;
        }
        *reinterpret_cast<float2*>(&s_samp[c * 64 + p0]) = sv;
    }
    __syncthreads();

    // ---- stage 4: einsum, per-warp 8 o-rows, 2 px per lane ----------------
    {
        const float4* w24 = (const float4*)w2;
        float ac[8][2];
        #pragma unroll
        for (int q = 0; q < 8; q++) { ac[q][0] = 0.0f; ac[q][1] = 0.0f; }

        #pragma unroll 2
        for (int c4 = 0; c4 < 64; c4 += 4) {
            const float2 sv0 = *reinterpret_cast<const float2*>(&s_samp[(c4 + 0) * 64 + p0]);
            const float2 sv1 = *reinterpret_cast<const float2*>(&s_samp[(c4 + 1) * 64 + p0]);
            const float2 sv2 = *reinterpret_cast<const float2*>(&s_samp[(c4 + 2) * 64 + p0]);
            const float2 sv3 = *reinterpret_cast<const float2*>(&s_samp[(c4 + 3) * 64 + p0]);
            const int cidx = c4 >> 2;
            #pragma unroll
            for (int q = 0; q < 8; q++) {
                const float4 wv = __ldg(&w24[(8 * wid + q) * 16 + cidx]);
                ac[q][0] += wv.x * sv0.x + wv.y * sv1.x + wv.z * sv2.x + wv.w * sv3.x;
                ac[q][1] += wv.x * sv0.y + wv.y * sv1.y + wv.z * sv2.y + wv.w * sv3.y;
            }
        }

        #pragma unroll
        for (int q = 0; q < 8; q++) {
            const int o = 8 * wid + q;
            const float bz = __ldg(bias + o);
            float2 ov;
            ov.x = ac[q][0] + bz;
            ov.y = ac[q][1] + bz;
            float* op = out + (((size_t)(b * OCH + o)) * HH + h) * WW + w0 + p0;
            *reinterpret_cast<float2*>(op) = ov;

            float s  = ov.x + ov.y;
            float s2 = ov.x * ov.x + ov.y * ov.y;
            #pragma unroll
            for (int m = 16; m >= 1; m >>= 1) {
                s  += __shfl_xor_sync(0xffffffffu, s,  m);
                s2 += __shfl_xor_sync(0xffffffffu, s2, m);
            }
            if (lane == 0) {
                g_psum  [o * NBLK + bid] = s;
                g_psumsq[o * NBLK + bid] = s2;
            }
        }
    }
}

__global__ void finalize_stats(const float* __restrict__ gamma,
                               const float* __restrict__ beta)
{
    const int o = blockIdx.x;
    __shared__ float ss[256];
    __shared__ float ss2[256];
    float s = 0.0f, s2 = 0.0f;
    for (int i = threadIdx.x; i < NBLK; i += 256) {
        s  += g_psum  [o * NBLK + i];
        s2 += g_psumsq[o * NBLK + i];
    }
    ss[threadIdx.x] = s; ss2[threadIdx.x] = s2;
    __syncthreads();
    for (int st = 128; st > 0; st >>= 1) {
        if (threadIdx.x < st) {
            ss [threadIdx.x] += ss [threadIdx.x + st];
            ss2[threadIdx.x] += ss2[threadIdx.x + st];
        }
        __syncthreads();
    }
    if (threadIdx.x == 0) {
        const float N = (float)(BB * HH * WW);
        const float mean = ss[0] / N;
        const float var  = ss2[0] / N - mean * mean;
        const float inv  = rsqrtf(var + 1e-5f);
        const float sc   = gamma[o] * inv;
        g_scale[o] = sc;
        g_shift[o] = beta[o] - mean * sc;
    }
}

__device__ __forceinline__ float gelu_exact(float v) {
    return v * normcdff(v);
}

__global__ __launch_bounds__(256)
void bn_gelu_kernel(float* __restrict__ out)
{
    const int i = blockIdx.x * blockDim.x + threadIdx.x;   // float4 index
    float4 v = reinterpret_cast<float4*>(out)[i];
    const int o = ((i * 4) >> 16) & 63;                    // plane = HW = 65536
    const float sc = g_scale[o];
    const float sh = g_shift[o];
    v.x = gelu_exact(v.x * sc + sh);
    v.y = gelu_exact(v.y * sc + sh);
    v.z = gelu_exact(v.z * sc + sh);
    v.w = gelu_exact(v.w * sc + sh);
    reinterpret_cast<float4*>(out)[i] = v;
}

extern "C" void kernel_launch(void* const* d_in, const int* in_sizes, int n_in,
                              void* d_out, int out_size)
{
    const float* x     = (const float*)d_in[0];
    const float* dww   = (const float*)d_in[1];
    const float* pww   = (const float*)d_in[2];
    const float* w2    = (const float*)d_in[3];
    const float* bias  = (const float*)d_in[4];
    const float* gamma = (const float*)d_in[5];
    const float* beta  = (const float*)d_in[6];
    float* out = (float*)d_out;

    dim3 grid(WW / PP, HH, BB);
    fused_deform_kernel<<<grid, 256>>>(x, dww, pww, w2, bias, out);
    finalize_stats<<<OCH, 256>>>(gamma, beta);

    const int n4 = (BB * OCH * HH * WW) / 4;
    bn_gelu_kernel<<<n4 / 256, 256>>>(out);
}

// round 6
// speedup vs baseline: 1.4018x; 1.4018x over previous
#include <cuda_runtime.h>
#include <cuda_bf16.h>
#include <math.h>
#include <cstdint>

#define BB 4
#define CC 64
#define OCH 64
#define HH 256
#define WW 256
#define PP 64
#define NBLK (BB * HH * (WW / PP))   // 4096

__device__ float g_psum  [OCH * NBLK];
__device__ float g_psumsq[OCH * NBLK];
__device__ float g_scale [OCH];
__device__ float g_shift [OCH];

// A fragments pre-packed for mma.sync.m16n8k16 (bf16 hi/lo 3-chain, K_ext=192)
// layout: [(mt*12 + ks)*32 + lane] -> uint4 (a0,a1,a2,a3)
__device__ uint4 g_Apack2[12 * 12 * 32];   // pw  (192x64)
__device__ uint4 g_Apack4[ 4 * 12 * 32];   // w2  ( 64x64)

// smem (floats): B tile 64px x 68 words, then om 192 rows x 68
#define BW 68
#define OM_OFF (64 * BW)                    // 4352 floats
#define SMEM_BYTES 81920                    // force 2 CTAs/SM, keep L1 alive

__device__ __forceinline__ uint32_t bfpack(__nv_bfloat16 a, __nv_bfloat16 b) {
    return (uint32_t)__bfloat16_as_ushort(a) | ((uint32_t)__bfloat16_as_ushort(b) << 16);
}

__device__ __forceinline__ uint32_t wpack(const float* W, int r, int c, bool lo) {
    float v0 = W[r * 64 + c], v1 = W[r * 64 + c + 1];
    __nv_bfloat16 h0 = __float2bfloat16(v0), h1 = __float2bfloat16(v1);
    if (lo) {
        h0 = __float2bfloat16(v0 - __bfloat162float(h0));
        h1 = __float2bfloat16(v1 - __bfloat162float(h1));
    }
    return bfpack(h0, h1);
}

// prep: build A fragments. ks 0-3: hi (vs T-hi), 4-7: lo (vs T-hi), 8-11: hi (vs T-lo)
__global__ void prep_weights(const float* __restrict__ pw, const float* __restrict__ w2)
{
    int idx = blockIdx.x * 256 + threadIdx.x;
    const float* W;
    uint4* dst;
    if (idx < 4608)      { W = pw; dst = g_Apack2; }
    else                 { idx -= 4608; if (idx >= 1536) return; W = w2; dst = g_Apack4; }
    const int mt = idx / 384;
    const int ks = (idx % 384) / 32;
    const int l  = idx % 32;
    const bool lo = ((ks >> 2) == 1);
    const int cb = (ks & 3) * 16 + (l & 3) * 2;
    const int r0 = mt * 16 + (l >> 2), r1 = r0 + 8;
    uint4 a;
    a.x = wpack(W, r0, cb,     lo);
    a.y = wpack(W, r1, cb,     lo);
    a.z = wpack(W, r0, cb + 8, lo);
    a.w = wpack(W, r1, cb + 8, lo);
    dst[idx] = a;
}

__device__ __forceinline__ void hmma(float d[4], uint4 a, uint32_t b0, uint32_t b1) {
    asm volatile(
        "mma.sync.aligned.m16n8k16.row.col.f32.bf16.bf16.f32 "
        "{%0,%1,%2,%3}, {%4,%5,%6,%7}, {%8,%9}, {%0,%1,%2,%3};"
        : "+f"(d[0]), "+f"(d[1]), "+f"(d[2]), "+f"(d[3])
        : "r"(a.x), "r"(a.y), "r"(a.z), "r"(a.w), "r"(b0), "r"(b1));
}

__device__ __forceinline__ float fetch_px(const float* __restrict__ img, int y, int x) {
    if ((unsigned)y < (unsigned)HH && (unsigned)x < (unsigned)WW)
        return __ldg(img + y * WW + x);
    return 0.0f;
}

__global__ __launch_bounds__(256, 2)
void fused_deform_kernel(const float* __restrict__ x,
                         const float* __restrict__ dw,
                         const float* __restrict__ bias,
                         float* __restrict__ out)
{
    extern __shared__ __align__(16) float sm[];
    uint32_t* sB   = (uint32_t*)sm;         // B tile: [p][k-word], stride BW
    float*    s_om = sm + OM_OFF;           // om rows [192][BW]
    float*    s_red  = s_om;                // overlay (om dead by stage-4 epilogue)
    float*    s_red2 = s_om + 512;

    const int tid  = threadIdx.x;
    const int wid  = tid >> 5;
    const int lane = tid & 31;
    const int w0   = blockIdx.x * PP;
    const int h    = blockIdx.y;
    const int b    = blockIdx.z;
    const int bid  = (blockIdx.z * gridDim.y + blockIdx.y) * gridDim.x + blockIdx.x;

    // ---- stage 1: depthwise conv -> bf16 hi/lo B tile ----------------------
    {
        const int g   = tid & 15;
        const int cb4 = (tid >> 4) * 4;      // 4 consecutive channels
        const int xs  = w0 + g * 4;
        float val[4][4];
        #pragma unroll
        for (int u = 0; u < 4; u++) {
            const int c = cb4 + u;
            const float* xc = x + ((size_t)(b * CC + c)) * (HH * WW);
            float w9[9];
            #pragma unroll
            for (int i = 0; i < 9; i++) w9[i] = __ldg(dw + c * 9 + i);
            float a0 = 0.f, a1 = 0.f, a2 = 0.f, a3 = 0.f;
            #pragma unroll
            for (int dy = -1; dy <= 1; dy++) {
                const int y = h + dy;
                if ((unsigned)y < (unsigned)HH) {
                    const float* row = xc + y * WW;
                    const float4 m = *reinterpret_cast<const float4*>(row + xs);
                    const float lm = (xs - 1 >= 0) ? __ldg(row + xs - 1) : 0.0f;
                    const float rm = (xs + 4 < WW) ? __ldg(row + xs + 4) : 0.0f;
                    const float wl = w9[(dy + 1) * 3 + 0];
                    const float wm = w9[(dy + 1) * 3 + 1];
                    const float wr = w9[(dy + 1) * 3 + 2];
                    a0 += wl * lm  + wm * m.x + wr * m.y;
                    a1 += wl * m.x + wm * m.y + wr * m.z;
                    a2 += wl * m.y + wm * m.z + wr * m.w;
                    a3 += wl * m.z + wm * m.w + wr * rm;
                }
            }
            val[u][0] = a0; val[u][1] = a1; val[u][2] = a2; val[u][3] = a3;
        }
        #pragma unroll
        for (int pr = 0; pr < 2; pr++)
            #pragma unroll
            for (int r = 0; r < 4; r++) {
                const int p = g * 4 + r;
                const float v0 = val[2 * pr][r], v1 = val[2 * pr + 1][r];
                const __nv_bfloat16 h0 = __float2bfloat16(v0);
                const __nv_bfloat16 h1 = __float2bfloat16(v1);
                const __nv_bfloat16 l0 = __float2bfloat16(v0 - __bfloat162float(h0));
                const __nv_bfloat16 l1 = __float2bfloat16(v1 - __bfloat162float(h1));
                sB[p * BW + (cb4 >> 1) + pr]      = bfpack(h0, h1);
                sB[p * BW + 32 + (cb4 >> 1) + pr] = bfpack(l0, l1);
            }
    }
    __syncthreads();

    // ---- stage 2: om = pw @ t  (HMMA, 3-chain) -----------------------------
    const int rg = lane >> 2;       // 0..7
    const int qd = lane & 3;        // 0..3
    const uint32_t* bbase = sB + (wid * 8 + rg) * BW + qd;
    const int col = wid * 8 + 2 * qd;

    #pragma unroll 1
    for (int j = 0; j < 6; j++) {
        float d0[4] = {0, 0, 0, 0}, d1[4] = {0, 0, 0, 0};
        const int mtA = 2 * j, mtB = 2 * j + 1;
        #pragma unroll
        for (int ks = 0; ks < 12; ks++) {
            const int kwb = (ks < 4) ? ks * 8 : (ks < 8) ? (ks - 4) * 8 : 32 + (ks - 8) * 8;
            const uint4 aA = __ldg(&g_Apack2[(mtA * 12 + ks) * 32 + lane]);
            const uint4 aB = __ldg(&g_Apack2[(mtB * 12 + ks) * 32 + lane]);
            const uint32_t b0 = bbase[kwb];
            const uint32_t b1 = bbase[kwb + 4];
            hmma(d0, aA, b0, b1);
            hmma(d1, aB, b0, b1);
        }
        #pragma unroll
        for (int t = 0; t < 2; t++) {
            float* dd = t ? d1 : d0;
            const int mt = 2 * j + t;
            const int r0 = mt * 16 + rg, r1 = r0 + 8;
            float v0 = dd[0], v1 = dd[1], v2 = dd[2], v3 = dd[3];
            if (mt < 8) {   // offsets: clip to +-64
                v0 = fminf(fmaxf(v0, -64.f), 64.f);
                v1 = fminf(fmaxf(v1, -64.f), 64.f);
                v2 = fminf(fmaxf(v2, -64.f), 64.f);
                v3 = fminf(fmaxf(v3, -64.f), 64.f);
            } else {        // modulator: 2*sigmoid
                v0 = 2.0f / (1.0f + __expf(-v0));
                v1 = 2.0f / (1.0f + __expf(-v1));
                v2 = 2.0f / (1.0f + __expf(-v2));
                v3 = 2.0f / (1.0f + __expf(-v3));
            }
            *reinterpret_cast<float2*>(&s_om[r0 * BW + col]) = make_float2(v0, v1);
            *reinterpret_cast<float2*>(&s_om[r1 * BW + col]) = make_float2(v2, v3);
        }
    }
    __syncthreads();

    // ---- stage 3: bilinear sampling * modulator -> B tile (reused) --------
    {
        const int p  = 32 * (wid & 1) + lane;     // pixel, consecutive across lanes
        const int cb = (wid >> 1) * 16;           // 16 channels per warp-pair
        #pragma unroll 2
        for (int i = 0; i < 8; i++) {
            const int c0 = cb + 2 * i;
            float v[2];
            #pragma unroll
            for (int s = 0; s < 2; s++) {
                const int c = c0 + s;
                const float offy = s_om[(2 * c)     * BW + p];
                const float offx = s_om[(2 * c + 1) * BW + p];
                const float md   = s_om[(128 + c)   * BW + p];
                const float sy = (float)h + offy;
                const float sx = (float)(w0 + p) + offx;
                const float y0f = floorf(sy);
                const float x0f = floorf(sx);
                const float wy = sy - y0f;
                const float wx = sx - x0f;
                const int y0  = (int)y0f;
                const int x0i = (int)x0f;
                const float* xc = x + ((size_t)(b * CC + c)) * (HH * WW);
                const float v00 = fetch_px(xc, y0,     x0i);
                const float v01 = fetch_px(xc, y0,     x0i + 1);
                const float v10 = fetch_px(xc, y0 + 1, x0i);
                const float v11 = fetch_px(xc, y0 + 1, x0i + 1);
                v[s] = ((1.0f - wy) * ((1.0f - wx) * v00 + wx * v01)
                      +         wy  * ((1.0f - wx) * v10 + wx * v11)) * md;
            }
            const __nv_bfloat16 h0 = __float2bfloat16(v[0]);
            const __nv_bfloat16 h1 = __float2bfloat16(v[1]);
            const __nv_bfloat16 l0 = __float2bfloat16(v[0] - __bfloat162float(h0));
            const __nv_bfloat16 l1 = __float2bfloat16(v[1] - __bfloat162float(h1));
            sB[p * BW + (c0 >> 1)]      = bfpack(h0, h1);
            sB[p * BW + 32 + (c0 >> 1)] = bfpack(l0, l1);
        }
    }
    __syncthreads();

    // ---- stage 4: out = w2 @ sampled + bias; BN partials -------------------
    #pragma unroll 1
    for (int j = 0; j < 2; j++) {
        float d0[4] = {0, 0, 0, 0}, d1[4] = {0, 0, 0, 0};
        const int mtA = 2 * j, mtB = 2 * j + 1;
        #pragma unroll
        for (int ks = 0; ks < 12; ks++) {
            const int kwb = (ks < 4) ? ks * 8 : (ks < 8) ? (ks - 4) * 8 : 32 + (ks - 8) * 8;
            const uint4 aA = __ldg(&g_Apack4[(mtA * 12 + ks) * 32 + lane]);
            const uint4 aB = __ldg(&g_Apack4[(mtB * 12 + ks) * 32 + lane]);
            const uint32_t b0 = bbase[kwb];
            const uint32_t b1 = bbase[kwb + 4];
            hmma(d0, aA, b0, b1);
            hmma(d1, aB, b0, b1);
        }
        #pragma unroll
        for (int t = 0; t < 2; t++) {
            float* dd = t ? d1 : d0;
            const int mt = 2 * j + t;
            const int r0 = mt * 16 + rg, r1 = r0 + 8;
            const float bz0 = __ldg(bias + r0);
            const float bz1 = __ldg(bias + r1);
            const float v0 = dd[0] + bz0, v1 = dd[1] + bz0;
            const float v2 = dd[2] + bz1, v3 = dd[3] + bz1;
            float* o0 = out + (((size_t)(b * OCH + r0)) * HH + h) * WW + w0 + col;
            float* o1 = out + (((size_t)(b * OCH + r1)) * HH + h) * WW + w0 + col;
            *reinterpret_cast<float2*>(o0) = make_float2(v0, v1);
            *reinterpret_cast<float2*>(o1) = make_float2(v2, v3);

            float sa = v0 + v1,           sq0 = v0 * v0 + v1 * v1;
            float sb = v2 + v3,           sq1 = v2 * v2 + v3 * v3;
            #pragma unroll
            for (int m = 1; m <= 2; m <<= 1) {
                sa  += __shfl_xor_sync(0xffffffffu, sa,  m);
                sq0 += __shfl_xor_sync(0xffffffffu, sq0, m);
                sb  += __shfl_xor_sync(0xffffffffu, sb,  m);
                sq1 += __shfl_xor_sync(0xffffffffu, sq1, m);
            }
            if (qd == 0) {
                s_red [r0 * 8 + wid] = sa;  s_red2[r0 * 8 + wid] = sq0;
                s_red [r1 * 8 + wid] = sb;  s_red2[r1 * 8 + wid] = sq1;
            }
        }
    }
    __syncthreads();

    if (tid < 64) {
        float s = 0.f, s2 = 0.f;
        #pragma unroll
        for (int k = 0; k < 8; k++) { s += s_red[tid * 8 + k]; s2 += s_red2[tid * 8 + k]; }
        g_psum  [tid * NBLK + bid] = s;
        g_psumsq[tid * NBLK + bid] = s2;
    }
}

// ---------------- BN stats + apply ------------------------------------------
__global__ void finalize_stats(const float* __restrict__ gamma,
                               const float* __restrict__ beta)
{
    const int o = blockIdx.x;
    __shared__ float ss[256];
    __shared__ float ss2[256];
    float s = 0.0f, s2 = 0.0f;
    for (int i = threadIdx.x; i < NBLK; i += 256) {
        s  += g_psum  [o * NBLK + i];
        s2 += g_psumsq[o * NBLK + i];
    }
    ss[threadIdx.x] = s; ss2[threadIdx.x] = s2;
    __syncthreads();
    for (int st = 128; st > 0; st >>= 1) {
        if (threadIdx.x < st) {
            ss [threadIdx.x] += ss [threadIdx.x + st];
            ss2[threadIdx.x] += ss2[threadIdx.x + st];
        }
        __syncthreads();
    }
    if (threadIdx.x == 0) {
        const float N = (float)(BB * HH * WW);
        const float mean = ss[0] / N;
        const float var  = ss2[0] / N - mean * mean;
        const float inv  = rsqrtf(var + 1e-5f);
        const float sc   = gamma[o] * inv;
        g_scale[o] = sc;
        g_shift[o] = beta[o] - mean * sc;
    }
}

__device__ __forceinline__ float gelu_exact(float v) { return v * normcdff(v); }

__global__ __launch_bounds__(256)
void bn_gelu_kernel(float* __restrict__ out)
{
    const int i = blockIdx.x * blockDim.x + threadIdx.x;
    float4 v = reinterpret_cast<float4*>(out)[i];
    const int o = ((i * 4) >> 16) & 63;
    const float sc = g_scale[o];
    const float sh = g_shift[o];
    v.x = gelu_exact(v.x * sc + sh);
    v.y = gelu_exact(v.y * sc + sh);
    v.z = gelu_exact(v.z * sc + sh);
    v.w = gelu_exact(v.w * sc + sh);
    reinterpret_cast<float4*>(out)[i] = v;
}

extern "C" void kernel_launch(void* const* d_in, const int* in_sizes, int n_in,
                              void* d_out, int out_size)
{
    const float* x     = (const float*)d_in[0];
    const float* dww   = (const float*)d_in[1];
    const float* pww   = (const float*)d_in[2];
    const float* w2    = (const float*)d_in[3];
    const float* bias  = (const float*)d_in[4];
    const float* gamma = (const float*)d_in[5];
    const float* beta  = (const float*)d_in[6];
    float* out = (float*)d_out;

    cudaFuncSetAttribute(fused_deform_kernel,
                         cudaFuncAttributeMaxDynamicSharedMemorySize, SMEM_BYTES);

    prep_weights<<<24, 256>>>(pww, w2);
    dim3 grid(WW / PP, HH, BB);
    fused_deform_kernel<<<grid, 256, SMEM_BYTES>>>(x, dww, bias, out);
    finalize_stats<<<OCH, 256>>>(gamma, beta);

    const int n4 = (BB * OCH * HH * WW) / 4;
    bn_gelu_kernel<<<n4 / 256, 256>>>(out);
}

// round 7
// speedup vs baseline: 1.6512x; 1.1779x over previous
#include <cuda_runtime.h>
#include <cuda_bf16.h>
#include <math.h>
#include <cstdint>

#define BB 4
#define CC 64
#define OCH 64
#define HH 256
#define WW 256
#define PP 64
#define NBLK (BB * HH * (WW / PP))   // 4096

__device__ float g_psum  [OCH * NBLK];
__device__ float g_psumsq[OCH * NBLK];
__device__ float g_scale [OCH];
__device__ float g_shift [OCH];

// A fragments pre-packed for mma.sync.m16n8k16 (bf16 hi/lo 3-chain, K_ext=192)
__device__ uint4 g_Apack2[12 * 12 * 32];   // pw  (192x64)
__device__ uint4 g_Apack4[ 4 * 12 * 32];   // w2  ( 64x64)

// smem (floats): B tile 64px x 68 words, then om 192 rows x 68
#define BW 68
#define OM_OFF (64 * BW)                    // 4352 floats
#define SMEM_BYTES ((OM_OFF + 192 * BW) * 4)   // 69632 -> 3 CTAs/SM

__device__ __forceinline__ uint32_t bfpack(__nv_bfloat16 a, __nv_bfloat16 b) {
    return (uint32_t)__bfloat16_as_ushort(a) | ((uint32_t)__bfloat16_as_ushort(b) << 16);
}

__device__ __forceinline__ uint32_t wpack(const float* W, int r, int c, bool lo) {
    float v0 = W[r * 64 + c], v1 = W[r * 64 + c + 1];
    __nv_bfloat16 h0 = __float2bfloat16(v0), h1 = __float2bfloat16(v1);
    if (lo) {
        h0 = __float2bfloat16(v0 - __bfloat162float(h0));
        h1 = __float2bfloat16(v1 - __bfloat162float(h1));
    }
    return bfpack(h0, h1);
}

// prep: A fragments. ks 0-3: hi (vs T-hi), 4-7: lo (vs T-hi), 8-11: hi (vs T-lo)
__global__ void prep_weights(const float* __restrict__ pw, const float* __restrict__ w2)
{
    int idx = blockIdx.x * 256 + threadIdx.x;
    const float* W;
    uint4* dst;
    if (idx < 4608)      { W = pw; dst = g_Apack2; }
    else                 { idx -= 4608; if (idx >= 1536) return; W = w2; dst = g_Apack4; }
    const int mt = idx / 384;
    const int ks = (idx % 384) / 32;
    const int l  = idx % 32;
    const bool lo = ((ks >> 2) == 1);
    const int cb = (ks & 3) * 16 + (l & 3) * 2;
    const int r0 = mt * 16 + (l >> 2), r1 = r0 + 8;
    uint4 a;
    a.x = wpack(W, r0, cb,     lo);
    a.y = wpack(W, r1, cb,     lo);
    a.z = wpack(W, r0, cb + 8, lo);
    a.w = wpack(W, r1, cb + 8, lo);
    dst[idx] = a;
}

__device__ __forceinline__ void hmma(float d[4], uint4 a, uint32_t b0, uint32_t b1) {
    asm volatile(
        "mma.sync.aligned.m16n8k16.row.col.f32.bf16.bf16.f32 "
        "{%0,%1,%2,%3}, {%4,%5,%6,%7}, {%8,%9}, {%0,%1,%2,%3};"
        : "+f"(d[0]), "+f"(d[1]), "+f"(d[2]), "+f"(d[3])
        : "r"(a.x), "r"(a.y), "r"(a.z), "r"(a.w), "r"(b0), "r"(b1));
}

__device__ __forceinline__ float fetch_px(const float* __restrict__ img, int y, int x) {
    if ((unsigned)y < (unsigned)HH && (unsigned)x < (unsigned)WW)
        return __ldg(img + y * WW + x);
    return 0.0f;
}

__global__ __launch_bounds__(256, 3)
void fused_deform_kernel(const float* __restrict__ x,
                         const float* __restrict__ dw,
                         const float* __restrict__ bias,
                         float* __restrict__ out)
{
    extern __shared__ __align__(16) float sm[];
    uint32_t* sB   = (uint32_t*)sm;         // B tile: [p][k-word], stride BW
    float*    s_om = sm + OM_OFF;           // om rows [192][BW]
    float*    s_red  = s_om;                // overlay (om dead by stage-4 epilogue)
    float*    s_red2 = s_om + 512;

    const int tid  = threadIdx.x;
    const int wid  = tid >> 5;
    const int lane = tid & 31;
    const int w0   = blockIdx.x * PP;
    const int h    = blockIdx.y;
    const int b    = blockIdx.z;
    const int bid  = (blockIdx.z * gridDim.y + blockIdx.y) * gridDim.x + blockIdx.x;

    // ---- stage 1: depthwise conv -> bf16 hi/lo B tile ----------------------
    {
        const int g   = tid & 15;
        const int cb4 = (tid >> 4) * 4;
        const int xs  = w0 + g * 4;
        float val[4][4];
        #pragma unroll
        for (int u = 0; u < 4; u++) {
            const int c = cb4 + u;
            const float* xc = x + ((size_t)(b * CC + c)) * (HH * WW);
            float w9[9];
            #pragma unroll
            for (int i = 0; i < 9; i++) w9[i] = __ldg(dw + c * 9 + i);
            float a0 = 0.f, a1 = 0.f, a2 = 0.f, a3 = 0.f;
            #pragma unroll
            for (int dy = -1; dy <= 1; dy++) {
                const int y = h + dy;
                if ((unsigned)y < (unsigned)HH) {
                    const float* row = xc + y * WW;
                    const float4 m = *reinterpret_cast<const float4*>(row + xs);
                    const float lm = (xs - 1 >= 0) ? __ldg(row + xs - 1) : 0.0f;
                    const float rm = (xs + 4 < WW) ? __ldg(row + xs + 4) : 0.0f;
                    const float wl = w9[(dy + 1) * 3 + 0];
                    const float wm = w9[(dy + 1) * 3 + 1];
                    const float wr = w9[(dy + 1) * 3 + 2];
                    a0 += wl * lm  + wm * m.x + wr * m.y;
                    a1 += wl * m.x + wm * m.y + wr * m.z;
                    a2 += wl * m.y + wm * m.z + wr * m.w;
                    a3 += wl * m.z + wm * m.w + wr * rm;
                }
            }
            val[u][0] = a0; val[u][1] = a1; val[u][2] = a2; val[u][3] = a3;
        }
        #pragma unroll
        for (int pr = 0; pr < 2; pr++)
            #pragma unroll
            for (int r = 0; r < 4; r++) {
                const int p = g * 4 + r;
                const float v0 = val[2 * pr][r], v1 = val[2 * pr + 1][r];
                const __nv_bfloat16 h0 = __float2bfloat16(v0);
                const __nv_bfloat16 h1 = __float2bfloat16(v1);
                const __nv_bfloat16 l0 = __float2bfloat16(v0 - __bfloat162float(h0));
                const __nv_bfloat16 l1 = __float2bfloat16(v1 - __bfloat162float(h1));
                sB[p * BW + (cb4 >> 1) + pr]      = bfpack(h0, h1);
                sB[p * BW + 32 + (cb4 >> 1) + pr] = bfpack(l0, l1);
            }
    }
    __syncthreads();

    // ---- stage 2: om = pw @ t  (HMMA, 3-chain, B hoisted to registers) ----
    const int rg = lane >> 2;       // 0..7
    const int qd = lane & 3;        // 0..3
    const uint32_t* bbase = sB + (wid * 8 + rg) * BW + qd;
    const int col = wid * 8 + 2 * qd;

    {
        // 16 unique B words: k=0..3 hi (words k*8, k*8+4), k=0..3 lo (32+k*8, +4)
        uint32_t breg[16];
        #pragma unroll
        for (int k = 0; k < 4; k++) {
            breg[2 * k]     = bbase[k * 8];
            breg[2 * k + 1] = bbase[k * 8 + 4];
            breg[8 + 2 * k]     = bbase[32 + k * 8];
            breg[8 + 2 * k + 1] = bbase[32 + k * 8 + 4];
        }
        #pragma unroll 1
        for (int j = 0; j < 6; j++) {
            float d0[4] = {0, 0, 0, 0}, d1[4] = {0, 0, 0, 0};
            const int mtA = 2 * j, mtB = 2 * j + 1;
            #pragma unroll
            for (int ks = 0; ks < 12; ks++) {
                const int bi = (ks < 8) ? (ks & 3) : (ks - 4);   // 0..3 or 4..7
                const uint4 aA = __ldg(&g_Apack2[(mtA * 12 + ks) * 32 + lane]);
                const uint4 aB = __ldg(&g_Apack2[(mtB * 12 + ks) * 32 + lane]);
                hmma(d0, aA, breg[2 * bi], breg[2 * bi + 1]);
                hmma(d1, aB, breg[2 * bi], breg[2 * bi + 1]);
            }
            #pragma unroll
            for (int t = 0; t < 2; t++) {
                float* dd = t ? d1 : d0;
                const int mt = 2 * j + t;
                const int r0 = mt * 16 + rg, r1 = r0 + 8;
                float v0 = dd[0], v1 = dd[1], v2 = dd[2], v3 = dd[3];
                if (mt < 8) {
                    v0 = fminf(fmaxf(v0, -64.f), 64.f);
                    v1 = fminf(fmaxf(v1, -64.f), 64.f);
                    v2 = fminf(fmaxf(v2, -64.f), 64.f);
                    v3 = fminf(fmaxf(v3, -64.f), 64.f);
                } else {
                    v0 = 2.0f / (1.0f + __expf(-v0));
                    v1 = 2.0f / (1.0f + __expf(-v1));
                    v2 = 2.0f / (1.0f + __expf(-v2));
                    v3 = 2.0f / (1.0f + __expf(-v3));
                }
                *reinterpret_cast<float2*>(&s_om[r0 * BW + col]) = make_float2(v0, v1);
                *reinterpret_cast<float2*>(&s_om[r1 * BW + col]) = make_float2(v2, v3);
            }
        }
    }
    __syncthreads();

    // ---- stage 3: bilinear sampling * modulator -> B tile (reused) --------
    {
        const int p  = 32 * (wid & 1) + lane;
        const int cb = (wid >> 1) * 16;
        #pragma unroll 2
        for (int i = 0; i < 8; i++) {
            const int c0 = cb + 2 * i;
            float v[2];
            #pragma unroll
            for (int s = 0; s < 2; s++) {
                const int c = c0 + s;
                const float offy = s_om[(2 * c)     * BW + p];
                const float offx = s_om[(2 * c + 1) * BW + p];
                const float md   = s_om[(128 + c)   * BW + p];
                const float sy = (float)h + offy;
                const float sx = (float)(w0 + p) + offx;
                const float y0f = floorf(sy);
                const float x0f = floorf(sx);
                const float wy = sy - y0f;
                const float wx = sx - x0f;
                const int y0  = (int)y0f;
                const int x0i = (int)x0f;
                const float* xc = x + ((size_t)(b * CC + c)) * (HH * WW);
                const float v00 = fetch_px(xc, y0,     x0i);
                const float v01 = fetch_px(xc, y0,     x0i + 1);
                const float v10 = fetch_px(xc, y0 + 1, x0i);
                const float v11 = fetch_px(xc, y0 + 1, x0i + 1);
                v[s] = ((1.0f - wy) * ((1.0f - wx) * v00 + wx * v01)
                      +         wy  * ((1.0f - wx) * v10 + wx * v11)) * md;
            }
            const __nv_bfloat16 h0 = __float2bfloat16(v[0]);
            const __nv_bfloat16 h1 = __float2bfloat16(v[1]);
            const __nv_bfloat16 l0 = __float2bfloat16(v[0] - __bfloat162float(h0));
            const __nv_bfloat16 l1 = __float2bfloat16(v[1] - __bfloat162float(h1));
            sB[p * BW + (c0 >> 1)]      = bfpack(h0, h1);
            sB[p * BW + 32 + (c0 >> 1)] = bfpack(l0, l1);
        }
    }
    __syncthreads();

    // ---- stage 4: out = w2 @ sampled + bias; BN partials -------------------
    {
        uint32_t breg[16];
        #pragma unroll
        for (int k = 0; k < 4; k++) {
            breg[2 * k]     = bbase[k * 8];
            breg[2 * k + 1] = bbase[k * 8 + 4];
            breg[8 + 2 * k]     = bbase[32 + k * 8];
            breg[8 + 2 * k + 1] = bbase[32 + k * 8 + 4];
        }
        #pragma unroll 1
        for (int j = 0; j < 2; j++) {
            float d0[4] = {0, 0, 0, 0}, d1[4] = {0, 0, 0, 0};
            const int mtA = 2 * j, mtB = 2 * j + 1;
            #pragma unroll
            for (int ks = 0; ks < 12; ks++) {
                const int bi = (ks < 8) ? (ks & 3) : (ks - 4);
                const uint4 aA = __ldg(&g_Apack4[(mtA * 12 + ks) * 32 + lane]);
                const uint4 aB = __ldg(&g_Apack4[(mtB * 12 + ks) * 32 + lane]);
                hmma(d0, aA, breg[2 * bi], breg[2 * bi + 1]);
                hmma(d1, aB, breg[2 * bi], breg[2 * bi + 1]);
            }
            #pragma unroll
            for (int t = 0; t < 2; t++) {
                float* dd = t ? d1 : d0;
                const int mt = 2 * j + t;
                const int r0 = mt * 16 + rg, r1 = r0 + 8;
                const float bz0 = __ldg(bias + r0);
                const float bz1 = __ldg(bias + r1);
                const float v0 = dd[0] + bz0, v1 = dd[1] + bz0;
                const float v2 = dd[2] + bz1, v3 = dd[3] + bz1;
                float* o0 = out + (((size_t)(b * OCH + r0)) * HH + h) * WW + w0 + col;
                float* o1 = out + (((size_t)(b * OCH + r1)) * HH + h) * WW + w0 + col;
                *reinterpret_cast<float2*>(o0) = make_float2(v0, v1);
                *reinterpret_cast<float2*>(o1) = make_float2(v2, v3);

                float sa = v0 + v1,           sq0 = v0 * v0 + v1 * v1;
                float sb = v2 + v3,           sq1 = v2 * v2 + v3 * v3;
                #pragma unroll
                for (int m = 1; m <= 2; m <<= 1) {
                    sa  += __shfl_xor_sync(0xffffffffu, sa,  m);
                    sq0 += __shfl_xor_sync(0xffffffffu, sq0, m);
                    sb  += __shfl_xor_sync(0xffffffffu, sb,  m);
                    sq1 += __shfl_xor_sync(0xffffffffu, sq1, m);
                }
                if (qd == 0) {
                    s_red [r0 * 8 + wid] = sa;  s_red2[r0 * 8 + wid] = sq0;
                    s_red [r1 * 8 + wid] = sb;  s_red2[r1 * 8 + wid] = sq1;
                }
            }
        }
    }
    __syncthreads();

    if (tid < 64) {
        float s = 0.f, s2 = 0.f;
        #pragma unroll
        for (int k = 0; k < 8; k++) { s += s_red[tid * 8 + k]; s2 += s_red2[tid * 8 + k]; }
        g_psum  [tid * NBLK + bid] = s;
        g_psumsq[tid * NBLK + bid] = s2;
    }
}

// ---------------- BN stats + apply ------------------------------------------
__global__ void finalize_stats(const float* __restrict__ gamma,
                               const float* __restrict__ beta)
{
    const int o = blockIdx.x;
    __shared__ float ss[256];
    __shared__ float ss2[256];
    float s = 0.0f, s2 = 0.0f;
    for (int i = threadIdx.x; i < NBLK; i += 256) {
        s  += g_psum  [o * NBLK + i];
        s2 += g_psumsq[o * NBLK + i];
    }
    ss[threadIdx.x] = s; ss2[threadIdx.x] = s2;
    __syncthreads();
    for (int st = 128; st > 0; st >>= 1) {
        if (threadIdx.x < st) {
            ss [threadIdx.x] += ss [threadIdx.x + st];
            ss2[threadIdx.x] += ss2[threadIdx.x + st];
        }
        __syncthreads();
    }
    if (threadIdx.x == 0) {
        const float N = (float)(BB * HH * WW);
        const float mean = ss[0] / N;
        const float var  = ss2[0] / N - mean * mean;
        const float inv  = rsqrtf(var + 1e-5f);
        const float sc   = gamma[o] * inv;
        g_scale[o] = sc;
        g_shift[o] = beta[o] - mean * sc;
    }
}

__device__ __forceinline__ float gelu_exact(float v) { return v * normcdff(v); }

__global__ __launch_bounds__(256)
void bn_gelu_kernel(float* __restrict__ out)
{
    const int i = blockIdx.x * blockDim.x + threadIdx.x;
    float4 v = reinterpret_cast<float4*>(out)[i];
    const int o = ((i * 4) >> 16) & 63;
    const float sc = g_scale[o];
    const float sh = g_shift[o];
    v.x = gelu_exact(v.x * sc + sh);
    v.y = gelu_exact(v.y * sc + sh);
    v.z = gelu_exact(v.z * sc + sh);
    v.w = gelu_exact(v.w * sc + sh);
    reinterpret_cast<float4*>(out)[i] = v;
}

extern "C" void kernel_launch(void* const* d_in, const int* in_sizes, int n_in,
                              void* d_out, int out_size)
{
    const float* x     = (const float*)d_in[0];
    const float* dww   = (const float*)d_in[1];
    const float* pww   = (const float*)d_in[2];
    const float* w2    = (const float*)d_in[3];
    const float* bias  = (const float*)d_in[4];
    const float* gamma = (const float*)d_in[5];
    const float* beta  = (const float*)d_in[6];
    float* out = (float*)d_out;

    cudaFuncSetAttribute(fused_deform_kernel,
                         cudaFuncAttributeMaxDynamicSharedMemorySize, SMEM_BYTES);

    prep_weights<<<24, 256>>>(pww, w2);
    dim3 grid(WW / PP, HH, BB);
    fused_deform_kernel<<<grid, 256, SMEM_BYTES>>>(x, dww, bias, out);
    finalize_stats<<<OCH, 256>>>(gamma, beta);

    const int n4 = (BB * OCH * HH * WW) / 4;
    bn_gelu_kernel<<<n4 / 256, 256>>>(out);
}

// round 8
// speedup vs baseline: 1.8734x; 1.1346x over previous
#include <cuda_runtime.h>
#include <cuda_bf16.h>
#include <math.h>
#include <cstdint>

#define BB 4
#define CC 64
#define OCH 64
#define HH 256
#define WW 256
#define PP 64
#define NBLK (BB * HH * (WW / PP))   // 4096

__device__ float g_psum  [OCH * NBLK];
__device__ float g_psumsq[OCH * NBLK];
__device__ float g_scale [OCH];
__device__ float g_shift [OCH];

// A fragments pre-packed for mma.sync.m16n8k16 (bf16 hi/lo, K_ext layout)
// ks 0-3: hi, ks 4-7: lo  (chain 3 reuses hi fragments in-register)
__device__ uint4 g_Apack2[12 * 12 * 32];   // pw  (192x64)  (ks 8-11 slots unused)
__device__ uint4 g_Apack4[ 4 * 12 * 32];   // w2  ( 64x64)

#define BW 68
#define OM_OFF (64 * BW)                    // 4352 floats
#define SMEM_BYTES ((OM_OFF + 192 * BW) * 4)   // 69632 -> 3 CTAs/SM

__device__ __forceinline__ uint32_t bfpack(__nv_bfloat16 a, __nv_bfloat16 b) {
    return (uint32_t)__bfloat16_as_ushort(a) | ((uint32_t)__bfloat16_as_ushort(b) << 16);
}

__device__ __forceinline__ uint32_t wpack(const float* W, int r, int c, bool lo) {
    float v0 = W[r * 64 + c], v1 = W[r * 64 + c + 1];
    __nv_bfloat16 h0 = __float2bfloat16(v0), h1 = __float2bfloat16(v1);
    if (lo) {
        h0 = __float2bfloat16(v0 - __bfloat162float(h0));
        h1 = __float2bfloat16(v1 - __bfloat162float(h1));
    }
    return bfpack(h0, h1);
}

__global__ void prep_weights(const float* __restrict__ pw, const float* __restrict__ w2)
{
    int idx = blockIdx.x * 256 + threadIdx.x;
    const float* W;
    uint4* dst;
    if (idx < 4608)      { W = pw; dst = g_Apack2; }
    else                 { idx -= 4608; if (idx >= 1536) return; W = w2; dst = g_Apack4; }
    const int mt = idx / 384;
    const int ks = (idx % 384) / 32;
    const int l  = idx % 32;
    const bool lo = ((ks >> 2) == 1);
    const int cb = (ks & 3) * 16 + (l & 3) * 2;
    const int r0 = mt * 16 + (l >> 2), r1 = r0 + 8;
    uint4 a;
    a.x = wpack(W, r0, cb,     lo);
    a.y = wpack(W, r1, cb,     lo);
    a.z = wpack(W, r0, cb + 8, lo);
    a.w = wpack(W, r1, cb + 8, lo);
    dst[idx] = a;
}

__device__ __forceinline__ void hmma(float d[4], uint4 a, uint32_t b0, uint32_t b1) {
    asm volatile(
        "mma.sync.aligned.m16n8k16.row.col.f32.bf16.bf16.f32 "
        "{%0,%1,%2,%3}, {%4,%5,%6,%7}, {%8,%9}, {%0,%1,%2,%3};"
        : "+f"(d[0]), "+f"(d[1]), "+f"(d[2]), "+f"(d[3])
        : "r"(a.x), "r"(a.y), "r"(a.z), "r"(a.w), "r"(b0), "r"(b1));
}

__device__ __forceinline__ float fetch_px(const float* __restrict__ img, int y, int x) {
    if ((unsigned)y < (unsigned)HH && (unsigned)x < (unsigned)WW)
        return __ldg(img + y * WW + x);
    return 0.0f;
}

__global__ __launch_bounds__(256, 3)
void fused_deform_kernel(const float* __restrict__ x,
                         const float* __restrict__ dw,
                         const float* __restrict__ bias,
                         float* __restrict__ out)
{
    extern __shared__ __align__(16) float sm[];
    uint32_t* sB   = (uint32_t*)sm;         // B tile: [p][k-word], stride BW
    float*    s_om = sm + OM_OFF;           // om rows [192][BW]
    float*    s_red  = s_om;                // overlay (om dead by stage-4 epilogue)
    float*    s_red2 = s_om + 512;

    const int tid  = threadIdx.x;
    const int wid  = tid >> 5;
    const int lane = tid & 31;
    const int w0   = blockIdx.x * PP;
    const int h    = blockIdx.y;
    const int b    = blockIdx.z;
    const int bid  = (blockIdx.z * gridDim.y + blockIdx.y) * gridDim.x + blockIdx.x;

    // ---- stage 1: depthwise conv -> bf16 hi/lo B tile ----------------------
    {
        const int g   = tid & 15;
        const int cb4 = (tid >> 4) * 4;
        const int xs  = w0 + g * 4;
        float val[4][4];
        #pragma unroll
        for (int u = 0; u < 4; u++) {
            const int c = cb4 + u;
            const float* xc = x + ((size_t)(b * CC + c)) * (HH * WW);
            float w9[9];
            #pragma unroll
            for (int i = 0; i < 9; i++) w9[i] = __ldg(dw + c * 9 + i);
            float a0 = 0.f, a1 = 0.f, a2 = 0.f, a3 = 0.f;
            #pragma unroll
            for (int dy = -1; dy <= 1; dy++) {
                const int y = h + dy;
                if ((unsigned)y < (unsigned)HH) {
                    const float* row = xc + y * WW;
                    const float4 m = *reinterpret_cast<const float4*>(row + xs);
                    const float lm = (xs - 1 >= 0) ? __ldg(row + xs - 1) : 0.0f;
                    const float rm = (xs + 4 < WW) ? __ldg(row + xs + 4) : 0.0f;
                    const float wl = w9[(dy + 1) * 3 + 0];
                    const float wm = w9[(dy + 1) * 3 + 1];
                    const float wr = w9[(dy + 1) * 3 + 2];
                    a0 += wl * lm  + wm * m.x + wr * m.y;
                    a1 += wl * m.x + wm * m.y + wr * m.z;
                    a2 += wl * m.y + wm * m.z + wr * m.w;
                    a3 += wl * m.z + wm * m.w + wr * rm;
                }
            }
            val[u][0] = a0; val[u][1] = a1; val[u][2] = a2; val[u][3] = a3;
        }
        #pragma unroll
        for (int pr = 0; pr < 2; pr++)
            #pragma unroll
            for (int r = 0; r < 4; r++) {
                const int p = g * 4 + r;
                const float v0 = val[2 * pr][r], v1 = val[2 * pr + 1][r];
                const __nv_bfloat16 h0 = __float2bfloat16(v0);
                const __nv_bfloat16 h1 = __float2bfloat16(v1);
                const __nv_bfloat16 l0 = __float2bfloat16(v0 - __bfloat162float(h0));
                const __nv_bfloat16 l1 = __float2bfloat16(v1 - __bfloat162float(h1));
                sB[p * BW + (cb4 >> 1) + pr]      = bfpack(h0, h1);
                sB[p * BW + 32 + (cb4 >> 1) + pr] = bfpack(l0, l1);
            }
    }
    __syncthreads();

    // ---- stage 2: om = pw @ t  (HMMA 3-chain, hi A-frags reused) ----------
    const int rg = lane >> 2;       // 0..7
    const int qd = lane & 3;        // 0..3
    const uint32_t* bbase = sB + (wid * 8 + rg) * BW + qd;
    const int col = wid * 8 + 2 * qd;

    {
        uint32_t breg[16];
        #pragma unroll
        for (int k = 0; k < 4; k++) {
            breg[2 * k]         = bbase[k * 8];
            breg[2 * k + 1]     = bbase[k * 8 + 4];
            breg[8 + 2 * k]     = bbase[32 + k * 8];
            breg[8 + 2 * k + 1] = bbase[32 + k * 8 + 4];
        }
        #pragma unroll 1
        for (int mt = 0; mt < 12; mt++) {
            float d[4] = {0, 0, 0, 0};
            uint4 ahi[4];
            #pragma unroll
            for (int k = 0; k < 4; k++)
                ahi[k] = __ldg(&g_Apack2[(mt * 12 + k) * 32 + lane]);
            #pragma unroll
            for (int k = 0; k < 4; k++)                 // chain 1: Whi x Thi
                hmma(d, ahi[k], breg[2 * k], breg[2 * k + 1]);
            #pragma unroll
            for (int k = 0; k < 4; k++) {               // chain 2: Wlo x Thi
                const uint4 alo = __ldg(&g_Apack2[(mt * 12 + 4 + k) * 32 + lane]);
                hmma(d, alo, breg[2 * k], breg[2 * k + 1]);
            }
            #pragma unroll
            for (int k = 0; k < 4; k++)                 // chain 3: Whi x Tlo
                hmma(d, ahi[k], breg[8 + 2 * k], breg[8 + 2 * k + 1]);

            const int r0 = mt * 16 + rg, r1 = r0 + 8;
            float v0 = d[0], v1 = d[1], v2 = d[2], v3 = d[3];
            if (mt < 8) {
                v0 = fminf(fmaxf(v0, -64.f), 64.f);
                v1 = fminf(fmaxf(v1, -64.f), 64.f);
                v2 = fminf(fmaxf(v2, -64.f), 64.f);
                v3 = fminf(fmaxf(v3, -64.f), 64.f);
            } else {
                v0 = 2.0f / (1.0f + __expf(-v0));
                v1 = 2.0f / (1.0f + __expf(-v1));
                v2 = 2.0f / (1.0f + __expf(-v2));
                v3 = 2.0f / (1.0f + __expf(-v3));
            }
            *reinterpret_cast<float2*>(&s_om[r0 * BW + col]) = make_float2(v0, v1);
            *reinterpret_cast<float2*>(&s_om[r1 * BW + col]) = make_float2(v2, v3);
        }
    }
    __syncthreads();

    // ---- stage 3: bilinear sampling * modulator -> B tile (reused) --------
    {
        const int p  = 32 * (wid & 1) + lane;
        const int cb = (wid >> 1) * 16;
        #pragma unroll 2
        for (int i = 0; i < 8; i++) {
            const int c0 = cb + 2 * i;
            float v[2];
            #pragma unroll
            for (int s = 0; s < 2; s++) {
                const int c = c0 + s;
                const float offy = s_om[(2 * c)     * BW + p];
                const float offx = s_om[(2 * c + 1) * BW + p];
                const float md   = s_om[(128 + c)   * BW + p];
                const float sy = (float)h + offy;
                const float sx = (float)(w0 + p) + offx;
                const float y0f = floorf(sy);
                const float x0f = floorf(sx);
                const float wy = sy - y0f;
                const float wx = sx - x0f;
                const int y0  = (int)y0f;
                const int x0i = (int)x0f;
                const float* xc = x + ((size_t)(b * CC + c)) * (HH * WW);
                const float v00 = fetch_px(xc, y0,     x0i);
                const float v01 = fetch_px(xc, y0,     x0i + 1);
                const float v10 = fetch_px(xc, y0 + 1, x0i);
                const float v11 = fetch_px(xc, y0 + 1, x0i + 1);
                v[s] = ((1.0f - wy) * ((1.0f - wx) * v00 + wx * v01)
                      +         wy  * ((1.0f - wx) * v10 + wx * v11)) * md;
            }
            const __nv_bfloat16 h0 = __float2bfloat16(v[0]);
            const __nv_bfloat16 h1 = __float2bfloat16(v[1]);
            const __nv_bfloat16 l0 = __float2bfloat16(v[0] - __bfloat162float(h0));
            const __nv_bfloat16 l1 = __float2bfloat16(v[1] - __bfloat162float(h1));
            sB[p * BW + (c0 >> 1)]      = bfpack(h0, h1);
            sB[p * BW + 32 + (c0 >> 1)] = bfpack(l0, l1);
        }
    }
    __syncthreads();

    // ---- stage 4: out = w2 @ sampled + bias; BN partials -------------------
    {
        uint32_t breg[16];
        #pragma unroll
        for (int k = 0; k < 4; k++) {
            breg[2 * k]         = bbase[k * 8];
            breg[2 * k + 1]     = bbase[k * 8 + 4];
            breg[8 + 2 * k]     = bbase[32 + k * 8];
            breg[8 + 2 * k + 1] = bbase[32 + k * 8 + 4];
        }
        #pragma unroll 1
        for (int mt = 0; mt < 4; mt++) {
            float d[4] = {0, 0, 0, 0};
            uint4 ahi[4];
            #pragma unroll
            for (int k = 0; k < 4; k++)
                ahi[k] = __ldg(&g_Apack4[(mt * 12 + k) * 32 + lane]);
            #pragma unroll
            for (int k = 0; k < 4; k++)
                hmma(d, ahi[k], breg[2 * k], breg[2 * k + 1]);
            #pragma unroll
            for (int k = 0; k < 4; k++) {
                const uint4 alo = __ldg(&g_Apack4[(mt * 12 + 4 + k) * 32 + lane]);
                hmma(d, alo, breg[2 * k], breg[2 * k + 1]);
            }
            #pragma unroll
            for (int k = 0; k < 4; k++)
                hmma(d, ahi[k], breg[8 + 2 * k], breg[8 + 2 * k + 1]);

            const int r0 = mt * 16 + rg, r1 = r0 + 8;
            const float bz0 = __ldg(bias + r0);
            const float bz1 = __ldg(bias + r1);
            const float v0 = d[0] + bz0, v1 = d[1] + bz0;
            const float v2 = d[2] + bz1, v3 = d[3] + bz1;
            float* o0 = out + (((size_t)(b * OCH + r0)) * HH + h) * WW + w0 + col;
            float* o1 = out + (((size_t)(b * OCH + r1)) * HH + h) * WW + w0 + col;
            *reinterpret_cast<float2*>(o0) = make_float2(v0, v1);
            *reinterpret_cast<float2*>(o1) = make_float2(v2, v3);

            float sa = v0 + v1,           sq0 = v0 * v0 + v1 * v1;
            float sb = v2 + v3,           sq1 = v2 * v2 + v3 * v3;
            #pragma unroll
            for (int m = 1; m <= 2; m <<= 1) {
                sa  += __shfl_xor_sync(0xffffffffu, sa,  m);
                sq0 += __shfl_xor_sync(0xffffffffu, sq0, m);
                sb  += __shfl_xor_sync(0xffffffffu, sb,  m);
                sq1 += __shfl_xor_sync(0xffffffffu, sq1, m);
            }
            if (qd == 0) {
                s_red [r0 * 8 + wid] = sa;  s_red2[r0 * 8 + wid] = sq0;
                s_red [r1 * 8 + wid] = sb;  s_red2[r1 * 8 + wid] = sq1;
            }
        }
    }
    __syncthreads();

    if (tid < 64) {
        float s = 0.f, s2 = 0.f;
        #pragma unroll
        for (int k = 0; k < 8; k++) { s += s_red[tid * 8 + k]; s2 += s_red2[tid * 8 + k]; }
        g_psum  [tid * NBLK + bid] = s;
        g_psumsq[tid * NBLK + bid] = s2;
    }
}

// ---------------- BN stats + apply ------------------------------------------
__global__ void finalize_stats(const float* __restrict__ gamma,
                               const float* __restrict__ beta)
{
    const int o = blockIdx.x;
    __shared__ float ss[256];
    __shared__ float ss2[256];
    float s = 0.0f, s2 = 0.0f;
    for (int i = threadIdx.x; i < NBLK; i += 256) {
        s  += g_psum  [o * NBLK + i];
        s2 += g_psumsq[o * NBLK + i];
    }
    ss[threadIdx.x] = s; ss2[threadIdx.x] = s2;
    __syncthreads();
    for (int st = 128; st > 0; st >>= 1) {
        if (threadIdx.x < st) {
            ss [threadIdx.x] += ss [threadIdx.x + st];
            ss2[threadIdx.x] += ss2[threadIdx.x + st];
        }
        __syncthreads();
    }
    if (threadIdx.x == 0) {
        const float N = (float)(BB * HH * WW);
        const float mean = ss[0] / N;
        const float var  = ss2[0] / N - mean * mean;
        const float inv  = rsqrtf(var + 1e-5f);
        const float sc   = gamma[o] * inv;
        g_scale[o] = sc;
        g_shift[o] = beta[o] - mean * sc;
    }
}

// fast GELU (tanh form, saturating): max abs dev from exact ~3e-4
__device__ __forceinline__ float gelu_fast(float v) {
    const float t = 0.7978845608f * v * (1.0f + 0.044715f * v * v);
    const float e = __expf(2.0f * t);
    const float th = 1.0f - 2.0f / (e + 1.0f);    // tanh(t), exact at +-inf
    return 0.5f * v * (1.0f + th);
}

__global__ __launch_bounds__(256)
void bn_gelu_kernel(float* __restrict__ out)
{
    const int i = blockIdx.x * blockDim.x + threadIdx.x;
    float4 v = reinterpret_cast<float4*>(out)[i];
    const int o = ((i * 4) >> 16) & 63;
    const float sc = g_scale[o];
    const float sh = g_shift[o];
    v.x = gelu_fast(v.x * sc + sh);
    v.y = gelu_fast(v.y * sc + sh);
    v.z = gelu_fast(v.z * sc + sh);
    v.w = gelu_fast(v.w * sc + sh);
    reinterpret_cast<float4*>(out)[i] = v;
}

extern "C" void kernel_launch(void* const* d_in, const int* in_sizes, int n_in,
                              void* d_out, int out_size)
{
    const float* x     = (const float*)d_in[0];
    const float* dww   = (const float*)d_in[1];
    const float* pww   = (const float*)d_in[2];
    const float* w2    = (const float*)d_in[3];
    const float* bias  = (const float*)d_in[4];
    const float* gamma = (const float*)d_in[5];
    const float* beta  = (const float*)d_in[6];
    float* out = (float*)d_out;

    cudaFuncSetAttribute(fused_deform_kernel,
                         cudaFuncAttributeMaxDynamicSharedMemorySize, SMEM_BYTES);

    prep_weights<<<24, 256>>>(pww, w2);
    dim3 grid(WW / PP, HH, BB);
    fused_deform_kernel<<<grid, 256, SMEM_BYTES>>>(x, dww, bias, out);
    finalize_stats<<<OCH, 256>>>(gamma, beta);

    const int n4 = (BB * OCH * HH * WW) / 4;
    bn_gelu_kernel<<<n4 / 256, 256>>>(out);
}

// round 9
// speedup vs baseline: 1.9569x; 1.0446x over previous
#include <cuda_runtime.h>
#include <cuda_bf16.h>
#include <math.h>
#include <cstdint>

#define BB 4
#define CC 64
#define OCH 64
#define HH 256
#define WW 256
#define PP 64
#define NBLK (BB * HH * (WW / PP))   // 4096

__device__ float g_psum  [OCH * NBLK];
__device__ float g_psumsq[OCH * NBLK];
__device__ float g_scale [OCH];
__device__ float g_shift [OCH];

// A fragments for mma.sync.m16n8k16: ks 0-3 = hi, ks 4-7 = lo (chain 3 reuses hi)
__device__ uint4 g_Apack2[12 * 12 * 32];   // pw  (192x64)
__device__ uint4 g_Apack4[ 4 * 12 * 32];   // w2  ( 64x64)

#define BW 68
#define OM_OFF (64 * BW)                    // 4352 floats
#define SMEM_BYTES ((OM_OFF + 192 * BW) * 4)   // 69632 -> 3 CTAs/SM

__device__ __forceinline__ uint32_t bfpack(__nv_bfloat16 a, __nv_bfloat16 b) {
    return (uint32_t)__bfloat16_as_ushort(a) | ((uint32_t)__bfloat16_as_ushort(b) << 16);
}

__device__ __forceinline__ uint32_t wpack(const float* W, int r, int c, bool lo) {
    float v0 = W[r * 64 + c], v1 = W[r * 64 + c + 1];
    __nv_bfloat16 h0 = __float2bfloat16(v0), h1 = __float2bfloat16(v1);
    if (lo) {
        h0 = __float2bfloat16(v0 - __bfloat162float(h0));
        h1 = __float2bfloat16(v1 - __bfloat162float(h1));
    }
    return bfpack(h0, h1);
}

__global__ void prep_weights(const float* __restrict__ pw, const float* __restrict__ w2)
{
    int idx = blockIdx.x * 256 + threadIdx.x;
    const float* W;
    uint4* dst;
    if (idx < 4608)      { W = pw; dst = g_Apack2; }
    else                 { idx -= 4608; if (idx >= 1536) return; W = w2; dst = g_Apack4; }
    const int mt = idx / 384;
    const int ks = (idx % 384) / 32;
    const int l  = idx % 32;
    const bool lo = ((ks >> 2) == 1);
    const int cb = (ks & 3) * 16 + (l & 3) * 2;
    const int r0 = mt * 16 + (l >> 2), r1 = r0 + 8;
    uint4 a;
    a.x = wpack(W, r0, cb,     lo);
    a.y = wpack(W, r1, cb,     lo);
    a.z = wpack(W, r0, cb + 8, lo);
    a.w = wpack(W, r1, cb + 8, lo);
    dst[idx] = a;
}

__device__ __forceinline__ void hmma(float d[4], uint4 a, uint32_t b0, uint32_t b1) {
    asm volatile(
        "mma.sync.aligned.m16n8k16.row.col.f32.bf16.bf16.f32 "
        "{%0,%1,%2,%3}, {%4,%5,%6,%7}, {%8,%9}, {%0,%1,%2,%3};"
        : "+f"(d[0]), "+f"(d[1]), "+f"(d[2]), "+f"(d[3])
        : "r"(a.x), "r"(a.y), "r"(a.z), "r"(a.w), "r"(b0), "r"(b1));
}

__device__ __forceinline__ float fetch_px(const float* __restrict__ img, int y, int x) {
    if ((unsigned)y < (unsigned)HH && (unsigned)x < (unsigned)WW)
        return __ldg(img + y * WW + x);
    return 0.0f;
}

__global__ __launch_bounds__(256, 3)
void fused_deform_kernel(const float* __restrict__ x,
                         const float* __restrict__ dw,
                         const float* __restrict__ bias,
                         float* __restrict__ out)
{
    extern __shared__ __align__(16) float sm[];
    uint32_t* sB   = (uint32_t*)sm;         // B tile: [p][k-word], stride BW
    float*    s_om = sm + OM_OFF;           // om rows [192][BW]
    float*    s_red  = s_om;                // overlay (om dead by stage-4 epilogue)
    float*    s_red2 = s_om + 256;

    const int tid  = threadIdx.x;
    const int wid  = tid >> 5;
    const int lane = tid & 31;
    const int w0   = blockIdx.x * PP;
    const int h    = blockIdx.y;
    const int b    = blockIdx.z;
    const int bid  = (blockIdx.z * gridDim.y + blockIdx.y) * gridDim.x + blockIdx.x;

    // ---- stage 1: depthwise conv -> bf16 hi/lo B tile ----------------------
    {
        const int g   = tid & 15;
        const int cb4 = (tid >> 4) * 4;
        const int xs  = w0 + g * 4;
        float val[4][4];
        #pragma unroll
        for (int u = 0; u < 4; u++) {
            const int c = cb4 + u;
            const float* xc = x + ((size_t)(b * CC + c)) * (HH * WW);
            float w9[9];
            #pragma unroll
            for (int i = 0; i < 9; i++) w9[i] = __ldg(dw + c * 9 + i);
            float a0 = 0.f, a1 = 0.f, a2 = 0.f, a3 = 0.f;
            #pragma unroll
            for (int dy = -1; dy <= 1; dy++) {
                const int y = h + dy;
                if ((unsigned)y < (unsigned)HH) {
                    const float* row = xc + y * WW;
                    const float4 m = *reinterpret_cast<const float4*>(row + xs);
                    const float lm = (xs - 1 >= 0) ? __ldg(row + xs - 1) : 0.0f;
                    const float rm = (xs + 4 < WW) ? __ldg(row + xs + 4) : 0.0f;
                    const float wl = w9[(dy + 1) * 3 + 0];
                    const float wm = w9[(dy + 1) * 3 + 1];
                    const float wr = w9[(dy + 1) * 3 + 2];
                    a0 += wl * lm  + wm * m.x + wr * m.y;
                    a1 += wl * m.x + wm * m.y + wr * m.z;
                    a2 += wl * m.y + wm * m.z + wr * m.w;
                    a3 += wl * m.z + wm * m.w + wr * rm;
                }
            }
            val[u][0] = a0; val[u][1] = a1; val[u][2] = a2; val[u][3] = a3;
        }
        #pragma unroll
        for (int pr = 0; pr < 2; pr++)
            #pragma unroll
            for (int r = 0; r < 4; r++) {
                const int p = g * 4 + r;
                const float v0 = val[2 * pr][r], v1 = val[2 * pr + 1][r];
                const __nv_bfloat16 h0 = __float2bfloat16(v0);
                const __nv_bfloat16 h1 = __float2bfloat16(v1);
                const __nv_bfloat16 l0 = __float2bfloat16(v0 - __bfloat162float(h0));
                const __nv_bfloat16 l1 = __float2bfloat16(v1 - __bfloat162float(h1));
                sB[p * BW + (cb4 >> 1) + pr]      = bfpack(h0, h1);
                sB[p * BW + 32 + (cb4 >> 1) + pr] = bfpack(l0, l1);
            }
    }
    __syncthreads();

    const int rg = lane >> 2;       // 0..7
    const int qd = lane & 3;        // 0..3
    const int nthalf = wid >> 2;    // 0: px 0-31, 1: px 32-63

    // ---- stage 2: om = pw @ t  (warp = 3 mt x 4 ntiles, B resident 2 nt) --
    {
        const int mt0 = 3 * (wid & 3);
        #pragma unroll 1
        for (int pass = 0; pass < 2; pass++) {
            uint32_t breg[2][16];
            #pragma unroll
            for (int ntl = 0; ntl < 2; ntl++) {
                const int nt = nthalf * 4 + pass * 2 + ntl;
                const uint32_t* bb = sB + (nt * 8 + rg) * BW + qd;
                #pragma unroll
                for (int k = 0; k < 4; k++) {
                    breg[ntl][2 * k]         = bb[k * 8];
                    breg[ntl][2 * k + 1]     = bb[k * 8 + 4];
                    breg[ntl][8 + 2 * k]     = bb[32 + k * 8];
                    breg[ntl][8 + 2 * k + 1] = bb[32 + k * 8 + 4];
                }
            }
            #pragma unroll 1
            for (int i = 0; i < 3; i++) {
                const int mt = mt0 + i;
                uint4 ahi[4];
                #pragma unroll
                for (int k = 0; k < 4; k++)
                    ahi[k] = __ldg(&g_Apack2[(mt * 12 + k) * 32 + lane]);
                float d0[4] = {0, 0, 0, 0}, d1[4] = {0, 0, 0, 0};
                #pragma unroll
                for (int k = 0; k < 4; k++) {              // chain 1: Whi x Thi
                    hmma(d0, ahi[k], breg[0][2 * k], breg[0][2 * k + 1]);
                    hmma(d1, ahi[k], breg[1][2 * k], breg[1][2 * k + 1]);
                }
                #pragma unroll
                for (int k = 0; k < 4; k++) {              // chain 2: Wlo x Thi
                    const uint4 alo = __ldg(&g_Apack2[(mt * 12 + 4 + k) * 32 + lane]);
                    hmma(d0, alo, breg[0][2 * k], breg[0][2 * k + 1]);
                    hmma(d1, alo, breg[1][2 * k], breg[1][2 * k + 1]);
                }
                #pragma unroll
                for (int k = 0; k < 4; k++) {              // chain 3: Whi x Tlo
                    hmma(d0, ahi[k], breg[0][8 + 2 * k], breg[0][8 + 2 * k + 1]);
                    hmma(d1, ahi[k], breg[1][8 + 2 * k], breg[1][8 + 2 * k + 1]);
                }
                const int r0 = mt * 16 + rg, r1 = r0 + 8;
                #pragma unroll
                for (int ntl = 0; ntl < 2; ntl++) {
                    float* d = ntl ? d1 : d0;
                    const int col = (nthalf * 4 + pass * 2 + ntl) * 8 + 2 * qd;
                    float v0 = d[0], v1 = d[1], v2 = d[2], v3 = d[3];
                    if (mt < 8) {
                        v0 = fminf(fmaxf(v0, -64.f), 64.f);
                        v1 = fminf(fmaxf(v1, -64.f), 64.f);
                        v2 = fminf(fmaxf(v2, -64.f), 64.f);
                        v3 = fminf(fmaxf(v3, -64.f), 64.f);
                    } else {
                        v0 = 2.0f / (1.0f + __expf(-v0));
                        v1 = 2.0f / (1.0f + __expf(-v1));
                        v2 = 2.0f / (1.0f + __expf(-v2));
                        v3 = 2.0f / (1.0f + __expf(-v3));
                    }
                    *reinterpret_cast<float2*>(&s_om[r0 * BW + col]) = make_float2(v0, v1);
                    *reinterpret_cast<float2*>(&s_om[r1 * BW + col]) = make_float2(v2, v3);
                }
            }
        }
    }
    __syncthreads();

    // ---- stage 3: bilinear sampling * modulator -> B tile (reused) --------
    {
        const int p  = 32 * (wid & 1) + lane;
        const int cb = (wid >> 1) * 16;
        #pragma unroll 2
        for (int i = 0; i < 8; i++) {
            const int c0 = cb + 2 * i;
            float v[2];
            #pragma unroll
            for (int s = 0; s < 2; s++) {
                const int c = c0 + s;
                const float offy = s_om[(2 * c)     * BW + p];
                const float offx = s_om[(2 * c + 1) * BW + p];
                const float md   = s_om[(128 + c)   * BW + p];
                const float sy = (float)h + offy;
                const float sx = (float)(w0 + p) + offx;
                const float y0f = floorf(sy);
                const float x0f = floorf(sx);
                const float wy = sy - y0f;
                const float wx = sx - x0f;
                const int y0  = (int)y0f;
                const int x0i = (int)x0f;
                const float* xc = x + ((size_t)(b * CC + c)) * (HH * WW);
                const float v00 = fetch_px(xc, y0,     x0i);
                const float v01 = fetch_px(xc, y0,     x0i + 1);
                const float v10 = fetch_px(xc, y0 + 1, x0i);
                const float v11 = fetch_px(xc, y0 + 1, x0i + 1);
                v[s] = ((1.0f - wy) * ((1.0f - wx) * v00 + wx * v01)
                      +         wy  * ((1.0f - wx) * v10 + wx * v11)) * md;
            }
            const __nv_bfloat16 h0 = __float2bfloat16(v[0]);
            const __nv_bfloat16 h1 = __float2bfloat16(v[1]);
            const __nv_bfloat16 l0 = __float2bfloat16(v[0] - __bfloat162float(h0));
            const __nv_bfloat16 l1 = __float2bfloat16(v[1] - __bfloat162float(h1));
            sB[p * BW + (c0 >> 1)]      = bfpack(h0, h1);
            sB[p * BW + 32 + (c0 >> 1)] = bfpack(l0, l1);
        }
    }
    __syncthreads();

    // ---- stage 4: out = w2 @ sampled (warp = 1 mt x 4 nt); BN partials ----
    {
        const int mt = wid & 3;
        const int r0 = mt * 16 + rg, r1 = r0 + 8;
        const float bz0 = __ldg(bias + r0);
        const float bz1 = __ldg(bias + r1);
        float sa0 = 0.f, sq0 = 0.f, sa1 = 0.f, sq1 = 0.f;

        #pragma unroll 1
        for (int pass = 0; pass < 2; pass++) {
            uint32_t breg[2][16];
            #pragma unroll
            for (int ntl = 0; ntl < 2; ntl++) {
                const int nt = nthalf * 4 + pass * 2 + ntl;
                const uint32_t* bb = sB + (nt * 8 + rg) * BW + qd;
                #pragma unroll
                for (int k = 0; k < 4; k++) {
                    breg[ntl][2 * k]         = bb[k * 8];
                    breg[ntl][2 * k + 1]     = bb[k * 8 + 4];
                    breg[ntl][8 + 2 * k]     = bb[32 + k * 8];
                    breg[ntl][8 + 2 * k + 1] = bb[32 + k * 8 + 4];
                }
            }
            uint4 ahi[4];
            #pragma unroll
            for (int k = 0; k < 4; k++)
                ahi[k] = __ldg(&g_Apack4[(mt * 12 + k) * 32 + lane]);
            float d0[4] = {0, 0, 0, 0}, d1[4] = {0, 0, 0, 0};
            #pragma unroll
            for (int k = 0; k < 4; k++) {
                hmma(d0, ahi[k], breg[0][2 * k], breg[0][2 * k + 1]);
                hmma(d1, ahi[k], breg[1][2 * k], breg[1][2 * k + 1]);
            }
            #pragma unroll
            for (int k = 0; k < 4; k++) {
                const uint4 alo = __ldg(&g_Apack4[(mt * 12 + 4 + k) * 32 + lane]);
                hmma(d0, alo, breg[0][2 * k], breg[0][2 * k + 1]);
                hmma(d1, alo, breg[1][2 * k], breg[1][2 * k + 1]);
            }
            #pragma unroll
            for (int k = 0; k < 4; k++) {
                hmma(d0, ahi[k], breg[0][8 + 2 * k], breg[0][8 + 2 * k + 1]);
                hmma(d1, ahi[k], breg[1][8 + 2 * k], breg[1][8 + 2 * k + 1]);
            }
            #pragma unroll
            for (int ntl = 0; ntl < 2; ntl++) {
                float* d = ntl ? d1 : d0;
                const int col = (nthalf * 4 + pass * 2 + ntl) * 8 + 2 * qd;
                const float v0 = d[0] + bz0, v1 = d[1] + bz0;
                const float v2 = d[2] + bz1, v3 = d[3] + bz1;
                float* o0 = out + (((size_t)(b * OCH + r0)) * HH + h) * WW + w0 + col;
                float* o1 = out + (((size_t)(b * OCH + r1)) * HH + h) * WW + w0 + col;
                *reinterpret_cast<float2*>(o0) = make_float2(v0, v1);
                *reinterpret_cast<float2*>(o1) = make_float2(v2, v3);
                sa0 += v0 + v1;  sq0 += v0 * v0 + v1 * v1;
                sa1 += v2 + v3;  sq1 += v2 * v2 + v3 * v3;
            }
        }
        // reduce over qd (4 lanes share rg): warp's 32 px per o-row
        #pragma unroll
        for (int m = 1; m <= 2; m <<= 1) {
            sa0 += __shfl_xor_sync(0xffffffffu, sa0, m);
            sq0 += __shfl_xor_sync(0xffffffffu, sq0, m);
            sa1 += __shfl_xor_sync(0xffffffffu, sa1, m);
            sq1 += __shfl_xor_sync(0xffffffffu, sq1, m);
        }
        if (qd == 0) {
            s_red [r0 * 2 + nthalf] = sa0;  s_red2[r0 * 2 + nthalf] = sq0;
            s_red [r1 * 2 + nthalf] = sa1;  s_red2[r1 * 2 + nthalf] = sq1;
        }
    }
    __syncthreads();

    if (tid < 64) {
        g_psum  [tid * NBLK + bid] = s_red [tid * 2] + s_red [tid * 2 + 1];
        g_psumsq[tid * NBLK + bid] = s_red2[tid * 2] + s_red2[tid * 2 + 1];
    }
}

// ---------------- BN stats + apply ------------------------------------------
__global__ void finalize_stats(const float* __restrict__ gamma,
                               const float* __restrict__ beta)
{
    const int o = blockIdx.x;
    __shared__ float ss[256];
    __shared__ float ss2[256];
    float s = 0.0f, s2 = 0.0f;
    for (int i = threadIdx.x; i < NBLK; i += 256) {
        s  += g_psum  [o * NBLK + i];
        s2 += g_psumsq[o * NBLK + i];
    }
    ss[threadIdx.x] = s; ss2[threadIdx.x] = s2;
    __syncthreads();
    for (int st = 128; st > 0; st >>= 1) {
        if (threadIdx.x < st) {
            ss [threadIdx.x] += ss [threadIdx.x + st];
            ss2[threadIdx.x] += ss2[threadIdx.x + st];
        }
        __syncthreads();
    }
    if (threadIdx.x == 0) {
        const float N = (float)(BB * HH * WW);
        const float mean = ss[0] / N;
        const float var  = ss2[0] / N - mean * mean;
        const float inv  = rsqrtf(var + 1e-5f);
        const float sc   = gamma[o] * inv;
        g_scale[o] = sc;
        g_shift[o] = beta[o] - mean * sc;
    }
}

// fast GELU (tanh form, saturating): max abs dev from exact ~3e-4
__device__ __forceinline__ float gelu_fast(float v) {
    const float t = 0.7978845608f * v * (1.0f + 0.044715f * v * v);
    const float e = __expf(2.0f * t);
    const float th = 1.0f - 2.0f / (e + 1.0f);
    return 0.5f * v * (1.0f + th);
}

__global__ __launch_bounds__(256)
void bn_gelu_kernel(float* __restrict__ out)
{
    const int i = blockIdx.x * blockDim.x + threadIdx.x;
    float4 v = reinterpret_cast<float4*>(out)[i];
    const int o = ((i * 4) >> 16) & 63;
    const float sc = g_scale[o];
    const float sh = g_shift[o];
    v.x = gelu_fast(v.x * sc + sh);
    v.y = gelu_fast(v.y * sc + sh);
    v.z = gelu_fast(v.z * sc + sh);
    v.w = gelu_fast(v.w * sc + sh);
    reinterpret_cast<float4*>(out)[i] = v;
}

extern "C" void kernel_launch(void* const* d_in, const int* in_sizes, int n_in,
                              void* d_out, int out_size)
{
    const float* x     = (const float*)d_in[0];
    const float* dww   = (const float*)d_in[1];
    const float* pww   = (const float*)d_in[2];
    const float* w2    = (const float*)d_in[3];
    const float* bias  = (const float*)d_in[4];
    const float* gamma = (const float*)d_in[5];
    const float* beta  = (const float*)d_in[6];
    float* out = (float*)d_out;

    cudaFuncSetAttribute(fused_deform_kernel,
                         cudaFuncAttributeMaxDynamicSharedMemorySize, SMEM_BYTES);

    prep_weights<<<24, 256>>>(pww, w2);
    dim3 grid(WW / PP, HH, BB);
    fused_deform_kernel<<<grid, 256, SMEM_BYTES>>>(x, dww, bias, out);
    finalize_stats<<<OCH, 256>>>(gamma, beta);

    const int n4 = (BB * OCH * HH * WW) / 4;
    bn_gelu_kernel<<<n4 / 256, 256>>>(out);
}

// round 10
// speedup vs baseline: 2.1391x; 1.0931x over previous
#include <cuda_runtime.h>
#include <cuda_bf16.h>
#include <math.h>
#include <cstdint>

#define BB 4
#define CC 64
#define OCH 64
#define HH 256
#define WW 256
#define PP 64
#define NBLK (BB * HH * (WW / PP))   // 4096

__device__ float g_psum  [OCH * NBLK];
__device__ float g_psumsq[OCH * NBLK];
__device__ float g_scale [OCH];
__device__ float g_shift [OCH];

// A fragments for mma.sync.m16n8k16: ks 0-3 = hi, ks 4-7 = lo (chain 3 reuses hi)
__device__ uint4  g_Apack2[12 * 12 * 32];   // pw  (192x64)
__device__ uint4  g_Apack4[ 4 * 12 * 32];   // w2  ( 64x64)
__device__ float4 g_dwpack[CC * 3];         // dw 3x3 rows padded to float4

#define BW 68
#define OM_OFF (64 * BW)                    // 4352 floats
#define SMEM_BYTES ((OM_OFF + 192 * BW) * 4)   // 69632 -> 3 CTAs/SM

__device__ __forceinline__ uint32_t bfpack(__nv_bfloat16 a, __nv_bfloat16 b) {
    return (uint32_t)__bfloat16_as_ushort(a) | ((uint32_t)__bfloat16_as_ushort(b) << 16);
}

__device__ __forceinline__ uint32_t wpack(const float* W, int r, int c, bool lo) {
    float v0 = W[r * 64 + c], v1 = W[r * 64 + c + 1];
    __nv_bfloat16 h0 = __float2bfloat16(v0), h1 = __float2bfloat16(v1);
    if (lo) {
        h0 = __float2bfloat16(v0 - __bfloat162float(h0));
        h1 = __float2bfloat16(v1 - __bfloat162float(h1));
    }
    return bfpack(h0, h1);
}

__global__ void prep_weights(const float* __restrict__ pw, const float* __restrict__ w2,
                             const float* __restrict__ dw)
{
    int idx = blockIdx.x * 256 + threadIdx.x;
    if (idx >= 6144) {                       // dw pack: 64 ch x 3 rows
        idx -= 6144;
        if (idx < CC * 3) {
            const int c = idx / 3, r = idx % 3;
            g_dwpack[idx] = make_float4(dw[c * 9 + r * 3], dw[c * 9 + r * 3 + 1],
                                        dw[c * 9 + r * 3 + 2], 0.0f);
        }
        return;
    }
    const float* W;
    uint4* dst;
    if (idx < 4608)      { W = pw; dst = g_Apack2; }
    else                 { idx -= 4608; W = w2; dst = g_Apack4; }
    const int mt = idx / 384;
    const int ks = (idx % 384) / 32;
    const int l  = idx % 32;
    const bool lo = ((ks >> 2) == 1);
    const int cb = (ks & 3) * 16 + (l & 3) * 2;
    const int r0 = mt * 16 + (l >> 2), r1 = r0 + 8;
    uint4 a;
    a.x = wpack(W, r0, cb,     lo);
    a.y = wpack(W, r1, cb,     lo);
    a.z = wpack(W, r0, cb + 8, lo);
    a.w = wpack(W, r1, cb + 8, lo);
    dst[idx] = a;
}

__device__ __forceinline__ void hmma(float d[4], uint4 a, uint32_t b0, uint32_t b1) {
    asm volatile(
        "mma.sync.aligned.m16n8k16.row.col.f32.bf16.bf16.f32 "
        "{%0,%1,%2,%3}, {%4,%5,%6,%7}, {%8,%9}, {%0,%1,%2,%3};"
        : "+f"(d[0]), "+f"(d[1]), "+f"(d[2]), "+f"(d[3])
        : "r"(a.x), "r"(a.y), "r"(a.z), "r"(a.w), "r"(b0), "r"(b1));
}

__device__ __forceinline__ float fetch_px(const float* __restrict__ img, int y, int x) {
    if ((unsigned)y < (unsigned)HH && (unsigned)x < (unsigned)WW)
        return __ldg(img + y * WW + x);
    return 0.0f;
}

__device__ __forceinline__ float sigm2(float v) {
    return __fdividef(2.0f, 1.0f + __expf(-v));   // saturates correctly at +-inf
}

__global__ __launch_bounds__(256, 3)
void fused_deform_kernel(const float* __restrict__ x,
                         const float* __restrict__ bias,
                         float* __restrict__ out)
{
    extern __shared__ __align__(16) float sm[];
    uint32_t* sB   = (uint32_t*)sm;         // B tile: [p][k-word], stride BW
    float*    s_om = sm + OM_OFF;           // om rows [192][BW]
    float*    s_red  = s_om;                // overlay (om dead by stage-4 epilogue)
    float*    s_red2 = s_om + 256;

    const int tid  = threadIdx.x;
    const int wid  = tid >> 5;
    const int lane = tid & 31;
    const int w0   = blockIdx.x * PP;
    const int h    = blockIdx.y;
    const int b    = blockIdx.z;
    const int bid  = (blockIdx.z * gridDim.y + blockIdx.y) * gridDim.x + blockIdx.x;

    // ---- stage 1: depthwise conv -> bf16 hi/lo B tile ----------------------
    {
        const int g   = tid & 15;
        const int cb4 = (tid >> 4) * 4;
        const int xs  = w0 + g * 4;
        float val[4][4];
        #pragma unroll
        for (int u = 0; u < 4; u++) {
            const int c = cb4 + u;
            const float* xc = x + ((size_t)(b * CC + c)) * (HH * WW);
            float a0 = 0.f, a1 = 0.f, a2 = 0.f, a3 = 0.f;
            #pragma unroll
            for (int dy = -1; dy <= 1; dy++) {
                const int y = h + dy;
                if ((unsigned)y < (unsigned)HH) {
                    const float* row = xc + y * WW;
                    const float4 m = *reinterpret_cast<const float4*>(row + xs);
                    const float lm = (xs - 1 >= 0) ? __ldg(row + xs - 1) : 0.0f;
                    const float rm = (xs + 4 < WW) ? __ldg(row + xs + 4) : 0.0f;
                    const float4 w3 = __ldg(&g_dwpack[c * 3 + dy + 1]);
                    a0 += w3.x * lm  + w3.y * m.x + w3.z * m.y;
                    a1 += w3.x * m.x + w3.y * m.y + w3.z * m.z;
                    a2 += w3.x * m.y + w3.y * m.z + w3.z * m.w;
                    a3 += w3.x * m.z + w3.y * m.w + w3.z * rm;
                }
            }
            val[u][0] = a0; val[u][1] = a1; val[u][2] = a2; val[u][3] = a3;
        }
        #pragma unroll
        for (int pr = 0; pr < 2; pr++)
            #pragma unroll
            for (int r = 0; r < 4; r++) {
                const int p = g * 4 + r;
                const float v0 = val[2 * pr][r], v1 = val[2 * pr + 1][r];
                const __nv_bfloat16 h0 = __float2bfloat16(v0);
                const __nv_bfloat16 h1 = __float2bfloat16(v1);
                const __nv_bfloat16 l0 = __float2bfloat16(v0 - __bfloat162float(h0));
                const __nv_bfloat16 l1 = __float2bfloat16(v1 - __bfloat162float(h1));
                sB[p * BW + (cb4 >> 1) + pr]      = bfpack(h0, h1);
                sB[p * BW + 32 + (cb4 >> 1) + pr] = bfpack(l0, l1);
            }
    }
    __syncthreads();

    const int rg = lane >> 2;       // 0..7
    const int qd = lane & 3;        // 0..3
    const int nthalf = wid >> 2;    // 0: px 0-31, 1: px 32-63

    // ---- stage 2: om = pw @ t  (warp = 3 mt x 4 ntiles, B resident 2 nt) --
    {
        const int mt0 = 3 * (wid & 3);
        #pragma unroll 1
        for (int pass = 0; pass < 2; pass++) {
            uint32_t breg[2][16];
            #pragma unroll
            for (int ntl = 0; ntl < 2; ntl++) {
                const int nt = nthalf * 4 + pass * 2 + ntl;
                const uint32_t* bb = sB + (nt * 8 + rg) * BW + qd;
                #pragma unroll
                for (int k = 0; k < 4; k++) {
                    breg[ntl][2 * k]         = bb[k * 8];
                    breg[ntl][2 * k + 1]     = bb[k * 8 + 4];
                    breg[ntl][8 + 2 * k]     = bb[32 + k * 8];
                    breg[ntl][8 + 2 * k + 1] = bb[32 + k * 8 + 4];
                }
            }
            #pragma unroll 1
            for (int i = 0; i < 3; i++) {
                const int mt = mt0 + i;
                uint4 ahi[4];
                #pragma unroll
                for (int k = 0; k < 4; k++)
                    ahi[k] = __ldg(&g_Apack2[(mt * 12 + k) * 32 + lane]);
                float d0[4] = {0, 0, 0, 0}, d1[4] = {0, 0, 0, 0};
                #pragma unroll
                for (int k = 0; k < 4; k++) {              // chain 1: Whi x Thi
                    hmma(d0, ahi[k], breg[0][2 * k], breg[0][2 * k + 1]);
                    hmma(d1, ahi[k], breg[1][2 * k], breg[1][2 * k + 1]);
                }
                #pragma unroll
                for (int k = 0; k < 4; k++) {              // chain 2: Wlo x Thi
                    const uint4 alo = __ldg(&g_Apack2[(mt * 12 + 4 + k) * 32 + lane]);
                    hmma(d0, alo, breg[0][2 * k], breg[0][2 * k + 1]);
                    hmma(d1, alo, breg[1][2 * k], breg[1][2 * k + 1]);
                }
                #pragma unroll
                for (int k = 0; k < 4; k++) {              // chain 3: Whi x Tlo
                    hmma(d0, ahi[k], breg[0][8 + 2 * k], breg[0][8 + 2 * k + 1]);
                    hmma(d1, ahi[k], breg[1][8 + 2 * k], breg[1][8 + 2 * k + 1]);
                }
                const int r0 = mt * 16 + rg, r1 = r0 + 8;
                #pragma unroll
                for (int ntl = 0; ntl < 2; ntl++) {
                    float* d = ntl ? d1 : d0;
                    const int col = (nthalf * 4 + pass * 2 + ntl) * 8 + 2 * qd;
                    float v0 = d[0], v1 = d[1], v2 = d[2], v3 = d[3];
                    if (mt < 8) {
                        v0 = fminf(fmaxf(v0, -64.f), 64.f);
                        v1 = fminf(fmaxf(v1, -64.f), 64.f);
                        v2 = fminf(fmaxf(v2, -64.f), 64.f);
                        v3 = fminf(fmaxf(v3, -64.f), 64.f);
                    } else {
                        v0 = sigm2(v0);
                        v1 = sigm2(v1);
                        v2 = sigm2(v2);
                        v3 = sigm2(v3);
                    }
                    *reinterpret_cast<float2*>(&s_om[r0 * BW + col]) = make_float2(v0, v1);
                    *reinterpret_cast<float2*>(&s_om[r1 * BW + col]) = make_float2(v2, v3);
                }
            }
        }
    }
    __syncthreads();

    // ---- stage 3: bilinear sampling * modulator -> B tile (reused) --------
    {
        const int p  = 32 * (wid & 1) + lane;
        const int cb = (wid >> 1) * 16;
        #pragma unroll 2
        for (int i = 0; i < 8; i++) {
            const int c0 = cb + 2 * i;
            float v[2];
            #pragma unroll
            for (int s = 0; s < 2; s++) {
                const int c = c0 + s;
                const float offy = s_om[(2 * c)     * BW + p];
                const float offx = s_om[(2 * c + 1) * BW + p];
                const float md   = s_om[(128 + c)   * BW + p];
                const float sy = (float)h + offy;
                const float sx = (float)(w0 + p) + offx;
                const float y0f = floorf(sy);
                const float x0f = floorf(sx);
                const float wy = sy - y0f;
                const float wx = sx - x0f;
                const int y0  = (int)y0f;
                const int x0i = (int)x0f;
                const float* xc = x + ((size_t)(b * CC + c)) * (HH * WW);
                const float v00 = fetch_px(xc, y0,     x0i);
                const float v01 = fetch_px(xc, y0,     x0i + 1);
                const float v10 = fetch_px(xc, y0 + 1, x0i);
                const float v11 = fetch_px(xc, y0 + 1, x0i + 1);
                v[s] = ((1.0f - wy) * ((1.0f - wx) * v00 + wx * v01)
                      +         wy  * ((1.0f - wx) * v10 + wx * v11)) * md;
            }
            const __nv_bfloat16 h0 = __float2bfloat16(v[0]);
            const __nv_bfloat16 h1 = __float2bfloat16(v[1]);
            const __nv_bfloat16 l0 = __float2bfloat16(v[0] - __bfloat162float(h0));
            const __nv_bfloat16 l1 = __float2bfloat16(v[1] - __bfloat162float(h1));
            sB[p * BW + (c0 >> 1)]      = bfpack(h0, h1);
            sB[p * BW + 32 + (c0 >> 1)] = bfpack(l0, l1);
        }
    }
    __syncthreads();

    // ---- stage 4: out = w2 @ sampled (warp = 1 mt x 4 nt); BN partials ----
    {
        const int mt = wid & 3;
        const int r0 = mt * 16 + rg, r1 = r0 + 8;
        const float bz0 = __ldg(bias + r0);
        const float bz1 = __ldg(bias + r1);
        float sa0 = 0.f, sq0 = 0.f, sa1 = 0.f, sq1 = 0.f;

        #pragma unroll 1
        for (int pass = 0; pass < 2; pass++) {
            uint32_t breg[2][16];
            #pragma unroll
            for (int ntl = 0; ntl < 2; ntl++) {
                const int nt = nthalf * 4 + pass * 2 + ntl;
                const uint32_t* bb = sB + (nt * 8 + rg) * BW + qd;
                #pragma unroll
                for (int k = 0; k < 4; k++) {
                    breg[ntl][2 * k]         = bb[k * 8];
                    breg[ntl][2 * k + 1]     = bb[k * 8 + 4];
                    breg[ntl][8 + 2 * k]     = bb[32 + k * 8];
                    breg[ntl][8 + 2 * k + 1] = bb[32 + k * 8 + 4];
                }
            }
            uint4 ahi[4];
            #pragma unroll
            for (int k = 0; k < 4; k++)
                ahi[k] = __ldg(&g_Apack4[(mt * 12 + k) * 32 + lane]);
            float d0[4] = {0, 0, 0, 0}, d1[4] = {0, 0, 0, 0};
            #pragma unroll
            for (int k = 0; k < 4; k++) {
                hmma(d0, ahi[k], breg[0][2 * k], breg[0][2 * k + 1]);
                hmma(d1, ahi[k], breg[1][2 * k], breg[1][2 * k + 1]);
            }
            #pragma unroll
            for (int k = 0; k < 4; k++) {
                const uint4 alo = __ldg(&g_Apack4[(mt * 12 + 4 + k) * 32 + lane]);
                hmma(d0, alo, breg[0][2 * k], breg[0][2 * k + 1]);
                hmma(d1, alo, breg[1][2 * k], breg[1][2 * k + 1]);
            }
            #pragma unroll
            for (int k = 0; k < 4; k++) {
                hmma(d0, ahi[k], breg[0][8 + 2 * k], breg[0][8 + 2 * k + 1]);
                hmma(d1, ahi[k], breg[1][8 + 2 * k], breg[1][8 + 2 * k + 1]);
            }
            #pragma unroll
            for (int ntl = 0; ntl < 2; ntl++) {
                float* d = ntl ? d1 : d0;
                const int col = (nthalf * 4 + pass * 2 + ntl) * 8 + 2 * qd;
                const float v0 = d[0] + bz0, v1 = d[1] + bz0;
                const float v2 = d[2] + bz1, v3 = d[3] + bz1;
                float* o0 = out + (((size_t)(b * OCH + r0)) * HH + h) * WW + w0 + col;
                float* o1 = out + (((size_t)(b * OCH + r1)) * HH + h) * WW + w0 + col;
                *reinterpret_cast<float2*>(o0) = make_float2(v0, v1);
                *reinterpret_cast<float2*>(o1) = make_float2(v2, v3);
                sa0 += v0 + v1;  sq0 += v0 * v0 + v1 * v1;
                sa1 += v2 + v3;  sq1 += v2 * v2 + v3 * v3;
            }
        }
        #pragma unroll
        for (int m = 1; m <= 2; m <<= 1) {
            sa0 += __shfl_xor_sync(0xffffffffu, sa0, m);
            sq0 += __shfl_xor_sync(0xffffffffu, sq0, m);
            sa1 += __shfl_xor_sync(0xffffffffu, sa1, m);
            sq1 += __shfl_xor_sync(0xffffffffu, sq1, m);
        }
        if (qd == 0) {
            s_red [r0 * 2 + nthalf] = sa0;  s_red2[r0 * 2 + nthalf] = sq0;
            s_red [r1 * 2 + nthalf] = sa1;  s_red2[r1 * 2 + nthalf] = sq1;
        }
    }
    __syncthreads();

    if (tid < 64) {
        g_psum  [tid * NBLK + bid] = s_red [tid * 2] + s_red [tid * 2 + 1];
        g_psumsq[tid * NBLK + bid] = s_red2[tid * 2] + s_red2[tid * 2 + 1];
    }
}

// ---------------- BN stats + apply ------------------------------------------
__global__ void finalize_stats(const float* __restrict__ gamma,
                               const float* __restrict__ beta)
{
    const int o = blockIdx.x;
    __shared__ float ss[256];
    __shared__ float ss2[256];
    float s = 0.0f, s2 = 0.0f;
    for (int i = threadIdx.x; i < NBLK; i += 256) {
        s  += g_psum  [o * NBLK + i];
        s2 += g_psumsq[o * NBLK + i];
    }
    ss[threadIdx.x] = s; ss2[threadIdx.x] = s2;
    __syncthreads();
    for (int st = 128; st > 0; st >>= 1) {
        if (threadIdx.x < st) {
            ss [threadIdx.x] += ss [threadIdx.x + st];
            ss2[threadIdx.x] += ss2[threadIdx.x + st];
        }
        __syncthreads();
    }
    if (threadIdx.x == 0) {
        const float N = (float)(BB * HH * WW);
        const float mean = ss[0] / N;
        const float var  = ss2[0] / N - mean * mean;
        const float inv  = rsqrtf(var + 1e-5f);
        const float sc   = gamma[o] * inv;
        g_scale[o] = sc;
        g_shift[o] = beta[o] - mean * sc;
    }
}

// fast GELU (tanh form, saturating): max abs dev from exact ~3e-4
__device__ __forceinline__ float gelu_fast(float v) {
    const float t = 0.7978845608f * v * (1.0f + 0.044715f * v * v);
    const float e = __expf(2.0f * t);
    const float th = 1.0f - __fdividef(2.0f, e + 1.0f);
    return 0.5f * v * (1.0f + th);
}

__global__ __launch_bounds__(256)
void bn_gelu_kernel(float* __restrict__ out)
{
    const int i = blockIdx.x * blockDim.x + threadIdx.x;
    float4 v = reinterpret_cast<float4*>(out)[i];
    const int o = ((i * 4) >> 16) & 63;
    const float sc = g_scale[o];
    const float sh = g_shift[o];
    v.x = gelu_fast(v.x * sc + sh);
    v.y = gelu_fast(v.y * sc + sh);
    v.z = gelu_fast(v.z * sc + sh);
    v.w = gelu_fast(v.w * sc + sh);
    reinterpret_cast<float4*>(out)[i] = v;
}

extern "C" void kernel_launch(void* const* d_in, const int* in_sizes, int n_in,
                              void* d_out, int out_size)
{
    const float* x     = (const float*)d_in[0];
    const float* dww   = (const float*)d_in[1];
    const float* pww   = (const float*)d_in[2];
    const float* w2    = (const float*)d_in[3];
    const float* bias  = (const float*)d_in[4];
    const float* gamma = (const float*)d_in[5];
    const float* beta  = (const float*)d_in[6];
    float* out = (float*)d_out;

    cudaFuncSetAttribute(fused_deform_kernel,
                         cudaFuncAttributeMaxDynamicSharedMemorySize, SMEM_BYTES);

    prep_weights<<<25, 256>>>(pww, w2, dww);
    dim3 grid(WW / PP, HH, BB);
    fused_deform_kernel<<<grid, 256, SMEM_BYTES>>>(x, bias, out);
    finalize_stats<<<OCH, 256>>>(gamma, beta);

    const int n4 = (BB * OCH * HH * WW) / 4;
    bn_gelu_kernel<<<n4 / 256, 256>>>(out);
}